// round 9
// baseline (speedup 1.0000x reference)
#include <cuda_runtime.h>
#include <cuda_fp16.h>
#include <cstdint>

// ---------------- problem constants ----------------
#define BATCH 2
#define NPTS 100000
#define TOTPTS (BATCH * NPTS)
#define C0 256
#define C1 512
#define C2 1024
#define SP1 34                 // padded 32+2
#define NPAD1 (SP1*SP1*SP1)    // 39304
#define SP2 18                 // padded 16+2
#define NPAD2 (SP2*SP2*SP2)    // 5832
#define DST 132                // epilogue smem row stride (floats)
#define SROW 80                // staging smem row stride in BYTES (64B data + 16 pad)
#define STAGE_B 20480          // bytes per stage: A 10240 + B 10240
#define B_OFF 10240

// ---------------- device scratch ----------------
__device__ float  g_xpad[BATCH * NPAD1 * C0];    // fp32 scatter grid (atomics)
__device__ __half g_xh[BATCH * NPAD1 * C0];      // fp16 conv1 input
__device__ float  g_h[TOTPTS * 128];             // point hidden
__device__ int    g_flat[TOTPTS];                // padded voxel index
__device__ __half g_wk1[27 * C1 * C0];           // conv1 W [k][co][ci] fp16
__device__ __half g_wk2[27 * C2 * C1];           // conv2 W [k][co][ci] fp16
__device__ float  g_c1[BATCH * NPAD1 * C1];      // conv1 pre-pool pos-major fp32
__device__ __half g_l1h[BATCH * NPAD2 * C1];     // pooled l1, pos-major fp16
__device__ float  g_c2[BATCH * NPAD2 * C2];      // conv2 pre-pool pos-major fp32
__device__ float  g_l2[BATCH * C2 * 512];        // pooled l2, chan-major
__device__ float  g_WtT[8 * 1024 * 512];         // convT W (par,ci,co)

// ---------------- helpers ----------------
__device__ __forceinline__ uint32_t smem_u32p(const void* p) {
    uint32_t a;
    asm("{ .reg .u64 t; cvta.to.shared.u64 t, %1; cvt.u32.u64 %0, t; }" : "=r"(a) : "l"(p));
    return a;
}
__device__ __forceinline__ void mma_f16(float* c, const uint32_t* a, const uint32_t* b) {
    asm volatile(
        "mma.sync.aligned.m16n8k16.row.col.f32.f16.f16.f32 "
        "{%0,%1,%2,%3}, {%4,%5,%6,%7}, {%8,%9}, {%0,%1,%2,%3};\n"
        : "+f"(c[0]), "+f"(c[1]), "+f"(c[2]), "+f"(c[3])
        : "r"(a[0]), "r"(a[1]), "r"(a[2]), "r"(a[3]), "r"(b[0]), "r"(b[1]));
}
#define LDSM_X4(r0, r1, r2, r3, addr) \
    asm volatile("ldmatrix.sync.aligned.m8n8.x4.shared.b16 {%0,%1,%2,%3}, [%4];" \
        : "=r"(r0), "=r"(r1), "=r"(r2), "=r"(r3) : "r"(addr))
#define CP_ASYNC16(sa, ga, sz) \
    asm volatile("cp.async.cg.shared.global [%0], [%1], 16, %2;" :: "r"(sa), "l"(ga), "r"(sz) : "memory")
#define CP_COMMIT() asm volatile("cp.async.commit_group;" ::: "memory")
#define CP_WAIT2()  asm volatile("cp.async.wait_group 2;" ::: "memory")
#define CP_WAITALL() asm volatile("cp.async.wait_all;" ::: "memory")

// ---------------- zero scratch (replay-safe) ----------------
__global__ void zero_scratch_kernel() {
    float4* p1 = reinterpret_cast<float4*>(g_xpad);
    int n1 = (BATCH * NPAD1 * C0) / 4;
    for (int i = blockIdx.x * blockDim.x + threadIdx.x; i < n1; i += gridDim.x * blockDim.x)
        p1[i] = make_float4(0.f, 0.f, 0.f, 0.f);
    float4* p2 = reinterpret_cast<float4*>(g_l1h);
    int n2 = (BATCH * NPAD2 * C1) / 8;     // halves, 8 per float4
    for (int i = blockIdx.x * blockDim.x + threadIdx.x; i < n2; i += gridDim.x * blockDim.x)
        p2[i] = make_float4(0.f, 0.f, 0.f, 0.f);
}

// ---------------- pack fp32 grid -> fp16 ----------------
__global__ void pack_half_kernel(const float* __restrict__ src, __half* __restrict__ dst, long n4) {
    for (long i = (long)blockIdx.x * blockDim.x + threadIdx.x; i < n4; i += (long)gridDim.x * blockDim.x) {
        float4 v = reinterpret_cast<const float4*>(src)[i];
        __half2* d = reinterpret_cast<__half2*>(dst) + 2 * i;
        d[0] = __floats2half2_rn(v.x, v.y);
        d[1] = __floats2half2_rn(v.z, v.w);
    }
}

// ---------------- conv weight transpose [co][ci][27] -> [k][co][ci] fp16 ----------------
__global__ void wk_transpose_kernel(const float* __restrict__ w, __half* __restrict__ wk, int Cout, int Cin) {
    long total = (long)27 * Cout * Cin;
    for (long i = (long)blockIdx.x * blockDim.x + threadIdx.x; i < total; i += (long)gridDim.x * blockDim.x) {
        int ci = (int)(i % Cin);
        long r = i / Cin;
        int co = (int)(r % Cout);
        int k  = (int)(r / Cout);
        wk[i] = __float2half_rn(w[((long)co * Cin + ci) * 27 + k]);
    }
}

// ---------------- convT weight transpose (1024,512,2,2,2) -> (par,ci,co) ----------------
__global__ void wt_transpose_kernel(const float* __restrict__ Wt) {
    int i = blockIdx.x * blockDim.x + threadIdx.x;
    if (i >= 8 * 1024 * 512) return;
    int co = i & 511;
    int ci = (i >> 9) & 1023;
    int par = i >> 19;
    g_WtT[i] = Wt[ci * 4096 + co * 8 + par];
}

// ---------------- point MLP stage 1 ----------------
__global__ __launch_bounds__(256) void point_h_kernel(
    const float* __restrict__ pc, const float* __restrict__ W1, const float* __restrict__ b1)
{
    __shared__ float W1s[384];
    __shared__ float b1s[128];
    int tid = threadIdx.x;
    for (int i = tid; i < 384; i += 256) W1s[i] = W1[i];
    if (tid < 128) b1s[tid] = b1[tid];
    __syncthreads();

    int P = blockIdx.x * 8 + (tid >> 5);
    int lane = tid & 31;
    if (P >= TOTPTS) return;

    float x = pc[P * 3 + 0], y = pc[P * 3 + 1], z = pc[P * 3 + 2];
    int ix = (int)floorf((x + 1.0f) * 16.0f);
    int iy = (int)floorf((y + 1.0f) * 16.0f);
    int iz = (int)floorf((z + 1.0f) * 16.0f);
    float xcx = x - (ix * 0.0625f + 0.03125f - 1.0f);
    float xcy = y - (iy * 0.0625f + 0.03125f - 1.0f);
    float xcz = z - (iz * 0.0625f + 0.03125f - 1.0f);

    if (lane == 0) g_flat[P] = (ix + 1) * (SP1 * SP1) + (iy + 1) * SP1 + (iz + 1);  // padded pos

    float* hrow = g_h + (long)P * 128;
#pragma unroll
    for (int j = 0; j < 4; j++) {
        int o = lane + 32 * j;
        float v = W1s[o * 3 + 0] * xcx + W1s[o * 3 + 1] * xcy + W1s[o * 3 + 2] * xcz + b1s[o];
        hrow[o] = fmaxf(v, 0.0f);
    }
}

// ---------------- point MLP stage 2 + scatter-max (fp32 atomics) ----------------
// blockIdx.y selects 128-cout half -> 99 KB smem -> 2 CTAs/SM.
__global__ __launch_bounds__(256) void point_f_scatter_kernel(
    const float* __restrict__ W2, const float* __restrict__ b2)
{
    extern __shared__ float sm[];
    float* W2s = sm;                 // [k][o] stride 129 (o in 0..127)
    float* hs  = sm + 128 * 129;     // [k][p] stride 65
    int tid = threadIdx.x;
    int P0 = blockIdx.x * 64;
    int co0 = blockIdx.y << 7;

    for (int idx = tid; idx < 128 * 128; idx += 256) {
        int o = idx >> 7, k = idx & 127;
        W2s[k * 129 + o] = W2[(co0 + o) * 128 + k];
    }
    const float* hsrc = g_h + (long)P0 * 128;
    for (int idx = tid; idx < 64 * 128; idx += 256) {
        int p = idx >> 7, k = idx & 127;
        hs[k * 65 + p] = hsrc[idx];
    }
    __syncthreads();

    int cg = tid & 31;
    int pg = tid >> 5;
    float acc[8][4];
#pragma unroll
    for (int i = 0; i < 8; i++)
#pragma unroll
        for (int j = 0; j < 4; j++) acc[i][j] = 0.0f;

#pragma unroll 4
    for (int k = 0; k < 128; k++) {
        float hv[8], wv[4];
#pragma unroll
        for (int i = 0; i < 8; i++) hv[i] = hs[k * 65 + pg * 8 + i];
#pragma unroll
        for (int j = 0; j < 4; j++) wv[j] = W2s[k * 129 + cg + 32 * j];
#pragma unroll
        for (int i = 0; i < 8; i++)
#pragma unroll
            for (int j = 0; j < 4; j++) acc[i][j] = fmaf(hv[i], wv[j], acc[i][j]);
    }

    float bv[4];
#pragma unroll
    for (int j = 0; j < 4; j++) bv[j] = __ldg(&b2[co0 + cg + 32 * j]);

    int* gx = reinterpret_cast<int*>(g_xpad);
#pragma unroll
    for (int i = 0; i < 8; i++) {
        int P = P0 + pg * 8 + i;
        int b = P / NPTS;
        long base = ((long)b * NPAD1 + g_flat[P]) * C0 + co0;
#pragma unroll
        for (int j = 0; j < 4; j++) {
            float f = acc[i][j] + bv[j];
            if (f > 0.0f)
                atomicMax(&gx[base + cg + 32 * j], __float_as_int(f));
        }
    }
}

// ---------------- fp16 mma.sync implicit-GEMM conv3x3x3 (+bias+relu) ----------------
// CTA: M=128 co x N=128 positions; K = 27 taps x Cin in 32-ci chunks (2 k16 steps per chunk).
// 4-stage cp.async pipeline; ldmatrix.x4 fragment loads; 8 warps 2(M)x4(N).
__global__ __launch_bounds__(256, 2) void gemm_conv_h(
    const __half* __restrict__ wk,    // [27][Cout][Cin] fp16
    const __half* __restrict__ xp,    // [b][Npos][Cin]  fp16, zero-padded borders
    const float* __restrict__ bias,
    float* __restrict__ outp,         // [b][Npos][Cout] pre-pool, pos-major fp32
    int Cin, int ncShift, int Sp, int Npos, int Cout, int nbase)
{
    extern __shared__ float sh[];
    uint32_t sbase = smem_u32p(sh);

    int tid = threadIdx.x;
    int lane = tid & 31, wid = tid >> 5;
    int wm = wid >> 2, wn = wid & 3;
    int NB = nbase + (blockIdx.x << 7);
    int M0 = blockIdx.y << 7;
    long bq = (long)blockIdx.z * Npos;
    int total = 27 << ncShift;
    int ncMask = (1 << ncShift) - 1;
    int rowL = tid >> 1, seg32 = (tid & 1) << 5;   // row 0..127, 32B segment pair

    // ldmatrix per-lane byte offsets (within a stage); +32B for second k16 half
    uint32_t ofsA[4], ofsB[2];
#pragma unroll
    for (int fm = 0; fm < 4; fm++)
        ofsA[fm] = (uint32_t)(((wm << 6) + (fm << 4) + (lane & 15)) * SROW + ((lane >> 4) << 4));
#pragma unroll
    for (int j = 0; j < 2; j++) {
        int row = (wn << 5) + (j << 4) + (lane & 7) + ((lane >> 4) << 3);
        ofsB[j] = (uint32_t)(B_OFF + row * SROW + (((lane >> 3) & 1) << 4));
    }

    float acc[4][4][4];
#pragma unroll
    for (int fm = 0; fm < 4; fm++)
#pragma unroll
        for (int fn = 0; fn < 4; fn++)
#pragma unroll
            for (int r = 0; r < 4; r++) acc[fm][fn][r] = 0.0f;

    auto issue_chunk = [&](int c) {
        int stg = c & 3;
        int tap = c >> ncShift;
        int ci0 = (c & ncMask) << 5;
        int k0 = tap / 9; int rr = tap - 9 * k0; int k1 = rr / 3; int k2 = rr - 3 * k1;
        int drow = (k0 - 1) * Sp * Sp + (k1 - 1) * Sp + (k2 - 1);
        uint32_t stb = sbase + (uint32_t)stg * STAGE_B;
        uint32_t sa = stb + (uint32_t)rowL * SROW + seg32;
        const __half* ga = wk + ((long)tap * Cout + M0 + rowL) * Cin + ci0 + (seg32 >> 1);
        CP_ASYNC16(sa, ga, 16);
        CP_ASYNC16(sa + 16, ga + 8, 16);
        int gpos = NB + drow + rowL;
        uint32_t sb = stb + B_OFF + (uint32_t)rowL * SROW + seg32;
        int ok = ((unsigned)gpos < (unsigned)Npos) ? 16 : 0;
        int gp = gpos < 0 ? 0 : (gpos >= Npos ? Npos - 1 : gpos);
        const __half* gb = xp + (bq + gp) * Cin + ci0 + (seg32 >> 1);
        CP_ASYNC16(sb, gb, ok);
        CP_ASYNC16(sb + 16, gb + 8, ok);
        CP_COMMIT();
    };

    issue_chunk(0); issue_chunk(1); issue_chunk(2);

    for (int c = 0; c < total; c++) {
        CP_WAIT2();
        __syncthreads();
        if (c + 3 < total) issue_chunk(c + 3); else CP_COMMIT();

        uint32_t stb = sbase + (uint32_t)(c & 3) * STAGE_B;
#pragma unroll
        for (int kh = 0; kh < 2; kh++) {
            uint32_t ko = (uint32_t)(kh << 5);
            uint32_t af[4][4], bf[2][4];
#pragma unroll
            for (int fm = 0; fm < 4; fm++)
                LDSM_X4(af[fm][0], af[fm][1], af[fm][2], af[fm][3], stb + ofsA[fm] + ko);
#pragma unroll
            for (int j = 0; j < 2; j++)
                LDSM_X4(bf[j][0], bf[j][1], bf[j][2], bf[j][3], stb + ofsB[j] + ko);
#pragma unroll
            for (int fm = 0; fm < 4; fm++)
#pragma unroll
                for (int fn = 0; fn < 4; fn++)
                    mma_f16(acc[fm][fn], af[fm], &bf[fn >> 1][(fn & 1) << 1]);
        }
    }
    CP_WAITALL();

    // -------- epilogue: transpose via smem, bias+relu, coalesced stores --------
    __syncthreads();
    float* Dsh = sh;                                   // [128 n][DST]
    int g = lane >> 2, t = lane & 3;
#pragma unroll
    for (int fm = 0; fm < 4; fm++) {
        int m = (wm << 6) + (fm << 4) + g;
#pragma unroll
        for (int fn = 0; fn < 4; fn++) {
            int n = (wn << 5) + (fn << 3) + (t << 1);
            Dsh[n * DST + m]           = acc[fm][fn][0];
            Dsh[(n + 1) * DST + m]     = acc[fm][fn][1];
            Dsh[n * DST + m + 8]       = acc[fm][fn][2];
            Dsh[(n + 1) * DST + m + 8] = acc[fm][fn][3];
        }
    }
    __syncthreads();
    for (int i = tid; i < 4096; i += 256) {
        int n = i >> 5, cc = (i & 31) << 2;
        int pos = NB + n;
        if (pos < Npos) {
            float4 v = *reinterpret_cast<float4*>(&Dsh[n * DST + cc]);
            v.x = fmaxf(v.x + __ldg(&bias[M0 + cc + 0]), 0.f);
            v.y = fmaxf(v.y + __ldg(&bias[M0 + cc + 1]), 0.f);
            v.z = fmaxf(v.z + __ldg(&bias[M0 + cc + 2]), 0.f);
            v.w = fmaxf(v.w + __ldg(&bias[M0 + cc + 3]), 0.f);
            *reinterpret_cast<float4*>(outp + (bq + pos) * Cout + M0 + cc) = v;
        }
    }
}

// ---------------- pool1: g_c1 (34^3 pos-major) -> d_out l1 (fp32) + g_l1h (fp16) ----------------
__global__ __launch_bounds__(128) void pool1_kernel(float* __restrict__ dout) {
    int pp = blockIdx.x;              // pooled pos in 16^3
    int b = blockIdx.z;
    int P0 = pp >> 8, P1 = (pp >> 4) & 15, P2 = pp & 15;
    int co4 = threadIdx.x << 2;

    float4 m = make_float4(-1e30f, -1e30f, -1e30f, -1e30f);
#pragma unroll
    for (int a = 0; a < 8; a++) {
        int c = (2 * P0 + (a >> 2) + 1) * (SP1 * SP1) + (2 * P1 + ((a >> 1) & 1) + 1) * SP1 + (2 * P2 + (a & 1) + 1);
        float4 v = *reinterpret_cast<const float4*>(&g_c1[((long)b * NPAD1 + c) * C1 + co4]);
        m.x = fmaxf(m.x, v.x); m.y = fmaxf(m.y, v.y); m.z = fmaxf(m.z, v.z); m.w = fmaxf(m.w, v.w);
    }
    int pad2 = (P0 + 1) * (SP2 * SP2) + (P1 + 1) * SP2 + (P2 + 1);
    __half2* lh = reinterpret_cast<__half2*>(&g_l1h[((long)b * NPAD2 + pad2) * C1 + co4]);
    lh[0] = __floats2half2_rn(m.x, m.y);
    lh[1] = __floats2half2_rn(m.z, m.w);

    long ob = ((long)b * 1024 + co4) * 4096 + pp;
    dout[ob] = m.x; dout[ob + 4096] = m.y; dout[ob + 2 * 4096] = m.z; dout[ob + 3 * 4096] = m.w;
}

// ---------------- pool2: g_c2 (18^3 pos-major) -> g_l2 (chan-major 8^3) ----------------
__global__ __launch_bounds__(256) void pool2_kernel() {
    int pp = blockIdx.x;              // pooled pos in 8^3
    int b = blockIdx.z;
    int Q0 = pp >> 6, Q1 = (pp >> 3) & 7, Q2 = pp & 7;
    int co4 = threadIdx.x << 2;

    float4 m = make_float4(-1e30f, -1e30f, -1e30f, -1e30f);
#pragma unroll
    for (int a = 0; a < 8; a++) {
        int c = (2 * Q0 + (a >> 2) + 1) * (SP2 * SP2) + (2 * Q1 + ((a >> 1) & 1) + 1) * SP2 + (2 * Q2 + (a & 1) + 1);
        float4 v = *reinterpret_cast<const float4*>(&g_c2[((long)b * NPAD2 + c) * C2 + co4]);
        m.x = fmaxf(m.x, v.x); m.y = fmaxf(m.y, v.y); m.z = fmaxf(m.z, v.z); m.w = fmaxf(m.w, v.w);
    }
    long ob = ((long)b * 1024 + co4) * 512 + pp;
    g_l2[ob] = m.x; g_l2[ob + 512] = m.y; g_l2[ob + 2 * 512] = m.z; g_l2[ob + 3 * 512] = m.w;
}

// ---------------- convT: 8 parity GEMMs (FFMA) ----------------
__global__ __launch_bounds__(256) void convt_kernel(const float* __restrict__ bt, float* __restrict__ out) {
    __shared__ float w_sh[32 * 128];
    __shared__ float x_sh[32 * 64];
    int posT = blockIdx.x;
    int coT  = blockIdx.y;
    int bp   = blockIdx.z;
    int b = bp >> 3, par = bp & 7;
    int tid = threadIdx.x;
    int col = tid & 31, prow = tid >> 5;

    const float* wbase = g_WtT + (long)par * (1024 * 512);
    const float* xbase = g_l2 + (long)b * (C2 * 512);

    float acc[4][8];
#pragma unroll
    for (int jc = 0; jc < 4; jc++)
#pragma unroll
        for (int jp = 0; jp < 8; jp++) acc[jc][jp] = 0.0f;

    for (int ci0 = 0; ci0 < 1024; ci0 += 32) {
        __syncthreads();
        for (int idx = tid; idx < 32 * 128; idx += 256) {
            int k = idx >> 7, c = idx & 127;
            w_sh[idx] = wbase[(long)(ci0 + k) * 512 + coT * 128 + c];
        }
        for (int idx = tid; idx < 32 * 64; idx += 256) {
            int k = idx >> 6, p = idx & 63;
            x_sh[idx] = xbase[(long)(ci0 + k) * 512 + posT * 64 + p];
        }
        __syncthreads();
#pragma unroll 4
        for (int k = 0; k < 32; k++) {
            float xv[8], wv[4];
#pragma unroll
            for (int jp = 0; jp < 8; jp++) xv[jp] = x_sh[k * 64 + prow + 8 * jp];
#pragma unroll
            for (int jc = 0; jc < 4; jc++) wv[jc] = w_sh[k * 128 + col + 32 * jc];
#pragma unroll
            for (int jc = 0; jc < 4; jc++)
#pragma unroll
                for (int jp = 0; jp < 8; jp++) acc[jc][jp] = fmaf(wv[jc], xv[jp], acc[jc][jp]);
        }
    }

    int az = par >> 2, ay = (par >> 1) & 1, ax = par & 1;
#pragma unroll
    for (int jc = 0; jc < 4; jc++) {
        int co = coT * 128 + col + 32 * jc;
        float bv = __ldg(&bt[co]);
#pragma unroll
        for (int jp = 0; jp < 8; jp++) {
            int pos = posT * 64 + prow + 8 * jp;
            int iz = pos >> 6, iy = (pos >> 3) & 7, ix = pos & 7;
            int s = (2 * iz + az) * 256 + (2 * iy + ay) * 16 + (2 * ix + ax);
            out[((long)b * 1024 + 512 + co) * 4096 + s] = acc[jc][jp] + bv;
        }
    }
}

// ---------------- launcher ----------------
extern "C" void kernel_launch(void* const* d_in, const int* in_sizes, int n_in,
                              void* d_out, int out_size)
{
    const float* pc  = (const float*)d_in[0];
    const float* W1  = (const float*)d_in[1];
    const float* b1  = (const float*)d_in[2];
    const float* W2  = (const float*)d_in[3];
    const float* b2  = (const float*)d_in[4];
    const float* Wc1 = (const float*)d_in[5];
    const float* bc1 = (const float*)d_in[6];
    const float* Wc2 = (const float*)d_in[7];
    const float* bc2 = (const float*)d_in[8];
    const float* Wt  = (const float*)d_in[9];
    const float* bt  = (const float*)d_in[10];
    float* out = (float*)d_out;

    void *p_xpad, *p_xh, *p_wk1, *p_wk2, *p_c1, *p_l1h, *p_c2;
    cudaGetSymbolAddress(&p_xpad, g_xpad);
    cudaGetSymbolAddress(&p_xh, g_xh);
    cudaGetSymbolAddress(&p_wk1, g_wk1);
    cudaGetSymbolAddress(&p_wk2, g_wk2);
    cudaGetSymbolAddress(&p_c1, g_c1);
    cudaGetSymbolAddress(&p_l1h, g_l1h);
    cudaGetSymbolAddress(&p_c2, g_c2);

    const int smem_pf = (128 * 129 + 128 * 65) * 4;           // 99,328 B -> 2 CTAs/SM
    const int smem_gm = 4 * STAGE_B;                          // 81,920 B (>= epilogue 67,584)
    cudaFuncSetAttribute(point_f_scatter_kernel, cudaFuncAttributeMaxDynamicSharedMemorySize, smem_pf);
    cudaFuncSetAttribute(gemm_conv_h, cudaFuncAttributeMaxDynamicSharedMemorySize, smem_gm);

    // interior-only position ranges (everything pools read)
    const int NBASE1 = SP1 * SP1 + SP1 + 1;                   // 1191
    const int NT1 = (32 * (SP1 * SP1 + SP1 + 1) + 1 - NBASE1 + 127) / 128;  // 289
    const int NBASE2 = SP2 * SP2 + SP2 + 1;                   // 343
    const int NT2 = (16 * (SP2 * SP2 + SP2 + 1) + 1 - NBASE2 + 127) / 128;  // 41

    // 1. zero scatter targets (replay-safe)
    zero_scratch_kernel<<<2048, 256>>>();
    // 2. weight transposes (conv weights -> fp16 [k][co][ci])
    wt_transpose_kernel<<<(8 * 1024 * 512 + 255) / 256, 256>>>(Wt);
    wk_transpose_kernel<<<4096, 256>>>(Wc1, (__half*)p_wk1, C1, C0);
    wk_transpose_kernel<<<8192, 256>>>(Wc2, (__half*)p_wk2, C2, C1);
    // 3. point MLP + scatter (fp32 atomics)
    point_h_kernel<<<TOTPTS / 8, 256>>>(pc, W1, b1);
    point_f_scatter_kernel<<<dim3(TOTPTS / 64, 2), 256, smem_pf>>>(W2, b2);
    // 3b. pack fp32 grid -> fp16
    pack_half_kernel<<<2048, 256>>>((const float*)p_xpad, (__half*)p_xh, (long)(BATCH * NPAD1 * C0) / 4);
    // 4. conv1: fp16 mma GEMM over interior positions (32-ci chunks)
    gemm_conv_h<<<dim3(NT1, C1 / 128, BATCH), 256, smem_gm>>>(
        (const __half*)p_wk1, (const __half*)p_xh, bc1, (float*)p_c1, C0, 3, SP1, NPAD1, C1, NBASE1);
    // 5. pool1 -> d_out[:,0:512,:] (fp32) and g_l1h (fp16)
    pool1_kernel<<<dim3(4096, 1, BATCH), 128>>>(out);
    // 6. conv2: fp16 mma GEMM over interior positions (32-ci chunks)
    gemm_conv_h<<<dim3(NT2, C2 / 128, BATCH), 256, smem_gm>>>(
        (const __half*)p_wk2, (const __half*)p_l1h, bc2, (float*)p_c2, C1, 4, SP2, NPAD2, C2, NBASE2);
    // 7. pool2 -> g_l2
    pool2_kernel<<<dim3(512, 1, BATCH), 256>>>();
    // 8. convT -> d_out[:,512:1024,:]
    convt_kernel<<<dim3(8, 4, 16), 256>>>(bt, out);
}

// round 11
// speedup vs baseline: 1.2167x; 1.2167x over previous
#include <cuda_runtime.h>
#include <cuda_fp16.h>
#include <cstdint>

// ---------------- problem constants ----------------
#define BATCH 2
#define NPTS 100000
#define TOTPTS (BATCH * NPTS)
#define C0 256
#define C1 512
#define C2 1024
#define SP1 34                 // padded 32+2
#define NPAD1 (SP1*SP1*SP1)    // 39304
#define SP2 18                 // padded 16+2
#define NPAD2 (SP2*SP2*SP2)    // 5832
#define DST 132                // epilogue smem row stride (floats)
// halo-conv staging geometry (tile 8x(4)y(4)z, halo 10x6x6=360 rows)
#define AROW 48                // A smem row stride bytes (32B data + 16 pad)
#define BROW 48                // B smem row stride bytes
#define A_STAGE 6144           // 128*AROW
#define B_BUF_OFF 24576        // 4*A_STAGE
#define B_BUF 17280            // 360*BROW

// ---------------- device scratch ----------------
__device__ float  g_xpad[BATCH * NPAD1 * C0];    // fp32 scatter grid (atomics)
__device__ __half g_xh[BATCH * NPAD1 * C0];      // fp16 conv1 input
__device__ float  g_h[TOTPTS * 128];             // point hidden
__device__ int    g_flat[TOTPTS];                // padded voxel index
__device__ __half g_wk1[27 * C1 * C0];           // conv1 W [k][co][ci] fp16
__device__ __half g_wk2[27 * C2 * C1];           // conv2 W [k][co][ci] fp16
__device__ float  g_c1[BATCH * NPAD1 * C1];      // conv1 pre-pool pos-major fp32
__device__ __half g_l1h[BATCH * NPAD2 * C1];     // pooled l1, pos-major fp16
__device__ float  g_c2[BATCH * NPAD2 * C2];      // conv2 pre-pool pos-major fp32
__device__ float  g_l2[BATCH * C2 * 512];        // pooled l2, chan-major
__device__ float  g_WtT[8 * 1024 * 512];         // convT W (par,ci,co)

// ---------------- helpers ----------------
__device__ __forceinline__ uint32_t smem_u32p(const void* p) {
    uint32_t a;
    asm("{ .reg .u64 t; cvta.to.shared.u64 t, %1; cvt.u32.u64 %0, t; }" : "=r"(a) : "l"(p));
    return a;
}
__device__ __forceinline__ void mma_f16(float* c, const uint32_t* a, const uint32_t* b) {
    asm volatile(
        "mma.sync.aligned.m16n8k16.row.col.f32.f16.f16.f32 "
        "{%0,%1,%2,%3}, {%4,%5,%6,%7}, {%8,%9}, {%0,%1,%2,%3};\n"
        : "+f"(c[0]), "+f"(c[1]), "+f"(c[2]), "+f"(c[3])
        : "r"(a[0]), "r"(a[1]), "r"(a[2]), "r"(a[3]), "r"(b[0]), "r"(b[1]));
}
#define LDSM_X4(r0, r1, r2, r3, addr) \
    asm volatile("ldmatrix.sync.aligned.m8n8.x4.shared.b16 {%0,%1,%2,%3}, [%4];" \
        : "=r"(r0), "=r"(r1), "=r"(r2), "=r"(r3) : "r"(addr))
#define CP_ASYNC16(sa, ga) \
    asm volatile("cp.async.cg.shared.global [%0], [%1], 16;" :: "r"(sa), "l"(ga) : "memory")
#define CP_COMMIT() asm volatile("cp.async.commit_group;" ::: "memory")
#define CP_WAIT2()  asm volatile("cp.async.wait_group 2;" ::: "memory")
#define CP_WAITALL() asm volatile("cp.async.wait_all;" ::: "memory")

// ---------------- zero scratch (replay-safe) ----------------
__global__ void zero_scratch_kernel() {
    float4* p1 = reinterpret_cast<float4*>(g_xpad);
    int n1 = (BATCH * NPAD1 * C0) / 4;
    for (int i = blockIdx.x * blockDim.x + threadIdx.x; i < n1; i += gridDim.x * blockDim.x)
        p1[i] = make_float4(0.f, 0.f, 0.f, 0.f);
    float4* p2 = reinterpret_cast<float4*>(g_l1h);
    int n2 = (BATCH * NPAD2 * C1) / 8;
    for (int i = blockIdx.x * blockDim.x + threadIdx.x; i < n2; i += gridDim.x * blockDim.x)
        p2[i] = make_float4(0.f, 0.f, 0.f, 0.f);
}

// ---------------- pack fp32 grid -> fp16 ----------------
__global__ void pack_half_kernel(const float* __restrict__ src, __half* __restrict__ dst, long n4) {
    for (long i = (long)blockIdx.x * blockDim.x + threadIdx.x; i < n4; i += (long)gridDim.x * blockDim.x) {
        float4 v = reinterpret_cast<const float4*>(src)[i];
        __half2* d = reinterpret_cast<__half2*>(dst) + 2 * i;
        d[0] = __floats2half2_rn(v.x, v.y);
        d[1] = __floats2half2_rn(v.z, v.w);
    }
}

// ---------------- conv weight transpose [co][ci][27] -> [k][co][ci] fp16 ----------------
__global__ void wk_transpose_kernel(const float* __restrict__ w, __half* __restrict__ wk, int Cout, int Cin) {
    long total = (long)27 * Cout * Cin;
    for (long i = (long)blockIdx.x * blockDim.x + threadIdx.x; i < total; i += (long)gridDim.x * blockDim.x) {
        int ci = (int)(i % Cin);
        long r = i / Cin;
        int co = (int)(r % Cout);
        int k  = (int)(r / Cout);
        wk[i] = __float2half_rn(w[((long)co * Cin + ci) * 27 + k]);
    }
}

// ---------------- convT weight transpose (1024,512,2,2,2) -> (par,ci,co) ----------------
__global__ void wt_transpose_kernel(const float* __restrict__ Wt) {
    int i = blockIdx.x * blockDim.x + threadIdx.x;
    if (i >= 8 * 1024 * 512) return;
    int co = i & 511;
    int ci = (i >> 9) & 1023;
    int par = i >> 19;
    g_WtT[i] = Wt[ci * 4096 + co * 8 + par];
}

// ---------------- point MLP stage 1 ----------------
__global__ __launch_bounds__(256) void point_h_kernel(
    const float* __restrict__ pc, const float* __restrict__ W1, const float* __restrict__ b1)
{
    __shared__ float W1s[384];
    __shared__ float b1s[128];
    int tid = threadIdx.x;
    for (int i = tid; i < 384; i += 256) W1s[i] = W1[i];
    if (tid < 128) b1s[tid] = b1[tid];
    __syncthreads();

    int P = blockIdx.x * 8 + (tid >> 5);
    int lane = tid & 31;
    if (P >= TOTPTS) return;

    float x = pc[P * 3 + 0], y = pc[P * 3 + 1], z = pc[P * 3 + 2];
    int ix = (int)floorf((x + 1.0f) * 16.0f);
    int iy = (int)floorf((y + 1.0f) * 16.0f);
    int iz = (int)floorf((z + 1.0f) * 16.0f);
    float xcx = x - (ix * 0.0625f + 0.03125f - 1.0f);
    float xcy = y - (iy * 0.0625f + 0.03125f - 1.0f);
    float xcz = z - (iz * 0.0625f + 0.03125f - 1.0f);

    if (lane == 0) g_flat[P] = (ix + 1) * (SP1 * SP1) + (iy + 1) * SP1 + (iz + 1);

    float* hrow = g_h + (long)P * 128;
#pragma unroll
    for (int j = 0; j < 4; j++) {
        int o = lane + 32 * j;
        float v = W1s[o * 3 + 0] * xcx + W1s[o * 3 + 1] * xcy + W1s[o * 3 + 2] * xcz + b1s[o];
        hrow[o] = fmaxf(v, 0.0f);
    }
}

// ---------------- point MLP stage 2 + scatter-max (R8 version) ----------------
__global__ __launch_bounds__(256) void point_f_scatter_kernel(
    const float* __restrict__ W2, const float* __restrict__ b2)
{
    extern __shared__ float sm[];
    float* W2s = sm;                 // [k][o] stride 257
    float* hs  = sm + 128 * 257;     // [k][p] stride 65
    int tid = threadIdx.x;
    int P0 = blockIdx.x * 64;

    for (int idx = tid; idx < 256 * 128; idx += 256) {
        int o = idx >> 7, k = idx & 127;
        W2s[k * 257 + o] = W2[idx];
    }
    const float* hsrc = g_h + (long)P0 * 128;
    for (int idx = tid; idx < 64 * 128; idx += 256) {
        int p = idx >> 7, k = idx & 127;
        hs[k * 65 + p] = hsrc[idx];
    }
    __syncthreads();

    int cg = tid & 31;
    int pg = tid >> 5;
    float acc[8][8];
#pragma unroll
    for (int i = 0; i < 8; i++)
#pragma unroll
        for (int j = 0; j < 8; j++) acc[i][j] = 0.0f;

#pragma unroll 4
    for (int k = 0; k < 128; k++) {
        float hv[8], wv[8];
#pragma unroll
        for (int i = 0; i < 8; i++) hv[i] = hs[k * 65 + pg * 8 + i];
#pragma unroll
        for (int j = 0; j < 8; j++) wv[j] = W2s[k * 257 + cg + 32 * j];
#pragma unroll
        for (int i = 0; i < 8; i++)
#pragma unroll
            for (int j = 0; j < 8; j++) acc[i][j] = fmaf(hv[i], wv[j], acc[i][j]);
    }

    float bv[8];
#pragma unroll
    for (int j = 0; j < 8; j++) bv[j] = __ldg(&b2[cg + 32 * j]);

    int* gx = reinterpret_cast<int*>(g_xpad);
#pragma unroll
    for (int i = 0; i < 8; i++) {
        int P = P0 + pg * 8 + i;
        int b = P / NPTS;
        long base = ((long)b * NPAD1 + g_flat[P]) * C0;
#pragma unroll
        for (int j = 0; j < 8; j++) {
            float f = acc[i][j] + bv[j];
            if (f > 0.0f)
                atomicMax(&gx[base + cg + 32 * j], __float_as_int(f));
        }
    }
}

// ---------------- fp16 mma halo-tiled conv3x3x3 (+bias+relu) ----------------
// CTA: M=128 co x N = 8x4x4 = 128 positions. Per 16-ci chunk: B halo block
// (10x6x6=360 rows) loaded ONCE, reused by all 27 taps via per-lane ldmatrix
// addressing. A (one tap x 16 ci) in a 4-stage cp.async pipeline.
__global__ __launch_bounds__(256, 2) void gemm_conv_halo(
    const __half* __restrict__ wk,    // [27][Cout][Cin] fp16
    const __half* __restrict__ xp,    // [b][Sp^3][Cin]  fp16, zero ring
    const float* __restrict__ bias,
    float* __restrict__ outp,         // [b][Sp^3][Cout] pre-pool pos-major fp32
    int Cin, int nChunks, int Sp, int Cout, int ntx, int nty)
{
    extern __shared__ float sh[];
    uint32_t sbase = smem_u32p(sh);
    int tid = threadIdx.x;
    int lane = tid & 31, wid = tid >> 5;
    int wm = wid >> 2, wn = wid & 3;

    int t = blockIdx.x;
    int tix = t % ntx; int tr = t / ntx; int tiy = tr % nty; int tiz = tr / nty;
    int px0 = 1 + tix * 8, py0 = 1 + tiy * 4, pz0 = 1 + tiz * 4;
    int SPsq = Sp * Sp;
    long bq = (long)blockIdx.z * (Sp * SPsq);
    int M0 = blockIdx.y << 7;
    int posBase = pz0 * SPsq + py0 * Sp + px0;
    long row0 = (long)(pz0 - 1) * SPsq + (long)(py0 - 1) * Sp + (px0 - 1);
    int total = nChunks * 27;

    // A ldmatrix offsets (same map as validated R8 kernel, AROW stride)
    uint32_t ofsA[4];
#pragma unroll
    for (int fm = 0; fm < 4; fm++)
        ofsA[fm] = (uint32_t)(((wm << 6) + (fm << 4) + (lane & 15)) * AROW + ((lane >> 4) << 4));
    // B per-lane halo base rows (same n-map as R8, converted to 3D halo rows)
    uint32_t hofs[2];
    uint32_t kbyte = (uint32_t)(((lane >> 3) & 1) << 4);
#pragma unroll
    for (int j = 0; j < 2; j++) {
        int n = (wn << 5) + (j << 4) + (lane & 7) + ((lane >> 4) << 3);
        int nx = n & 7, ny = (n >> 3) & 3, nz = n >> 5;
        hofs[j] = (uint32_t)((nz * 60 + ny * 10 + nx) * BROW) + kbyte;
    }

    float acc[4][4][4];
#pragma unroll
    for (int fm = 0; fm < 4; fm++)
#pragma unroll
        for (int fn = 0; fn < 4; fn++)
#pragma unroll
            for (int r = 0; r < 4; r++) acc[fm][fn][r] = 0.0f;

    int rowA = tid >> 1, segA = tid & 1;

    auto issue_stage = [&](int sIdx, int c, int tap, bool withB, int cb) {
        uint32_t stA = sbase + (uint32_t)sIdx * A_STAGE;
        const __half* ga = wk + ((long)tap * Cout + M0 + rowA) * Cin + (c << 4) + (segA << 3);
        CP_ASYNC16(stA + (uint32_t)rowA * AROW + (segA << 4), ga);
        if (withB) {
            uint32_t stB = sbase + B_BUF_OFF + (uint32_t)(cb & 1) * B_BUF;
            for (int s = tid; s < 720; s += 256) {
                int hr = s >> 1, hseg = s & 1;
                int hz = hr / 60; int h2 = hr - hz * 60;
                int hy = h2 / 10; int hx = h2 - hy * 10;
                long gpos = row0 + (long)hz * SPsq + hy * Sp + hx;
                const __half* gb = xp + (bq + gpos) * Cin + (cb << 4) + (hseg << 3);
                CP_ASYNC16(stB + (uint32_t)hr * BROW + (hseg << 4), gb);
            }
        }
        CP_COMMIT();
    };

    // prologue: stages 0..2 (B(0) rides stage 0)
    issue_stage(0, 0, 0, true, 0);
    issue_stage(1, 0, 1, false, 0);
    issue_stage(2, 0, 2, false, 0);

    int cI = 0, tapI = 3;                 // next issue stage = 3
    int cU = 0, dxU = 0, dyU = 0, dzU = 0; // consume tap decomposition

    for (int u = 0; u < total; u++) {
        CP_WAIT2();
        __syncthreads();
        if (u + 3 < total) {
            bool wB = (tapI == 24) && (cI + 1 < nChunks);
            issue_stage((u + 3) & 3, cI, tapI, wB, cI + 1);
            if (++tapI == 27) { tapI = 0; cI++; }
        } else CP_COMMIT();

        uint32_t stA = sbase + (uint32_t)(u & 3) * A_STAGE;
        uint32_t stB = sbase + B_BUF_OFF + (uint32_t)(cU & 1) * B_BUF
                     + (uint32_t)((dzU * 60 + dyU * 10 + dxU) * BROW);
        uint32_t af[4][4], bf[2][4];
#pragma unroll
        for (int fm = 0; fm < 4; fm++)
            LDSM_X4(af[fm][0], af[fm][1], af[fm][2], af[fm][3], stA + ofsA[fm]);
#pragma unroll
        for (int j = 0; j < 2; j++)
            LDSM_X4(bf[j][0], bf[j][1], bf[j][2], bf[j][3], stB + hofs[j]);
#pragma unroll
        for (int fm = 0; fm < 4; fm++)
#pragma unroll
            for (int fn = 0; fn < 4; fn++)
                mma_f16(acc[fm][fn], af[fm], &bf[fn >> 1][(fn & 1) << 1]);

        if (++dxU == 3) { dxU = 0; if (++dyU == 3) { dyU = 0; if (++dzU == 3) { dzU = 0; cU++; } } }
    }
    CP_WAITALL();

    // -------- epilogue: transpose via smem, bias+relu, coalesced stores --------
    __syncthreads();
    float* Dsh = sh;                                   // [128 n][DST]
    int g = lane >> 2, tq = lane & 3;
#pragma unroll
    for (int fm = 0; fm < 4; fm++) {
        int m = (wm << 6) + (fm << 4) + g;
#pragma unroll
        for (int fn = 0; fn < 4; fn++) {
            int n = (wn << 5) + (fn << 3) + (tq << 1);
            Dsh[n * DST + m]           = acc[fm][fn][0];
            Dsh[(n + 1) * DST + m]     = acc[fm][fn][1];
            Dsh[n * DST + m + 8]       = acc[fm][fn][2];
            Dsh[(n + 1) * DST + m + 8] = acc[fm][fn][3];
        }
    }
    __syncthreads();
    for (int i = tid; i < 4096; i += 256) {
        int n = i >> 5, cc = (i & 31) << 2;
        int nx = n & 7, ny = (n >> 3) & 3, nz = n >> 5;
        long pos = posBase + (long)nz * SPsq + ny * Sp + nx;
        float4 v = *reinterpret_cast<float4*>(&Dsh[n * DST + cc]);
        v.x = fmaxf(v.x + __ldg(&bias[M0 + cc + 0]), 0.f);
        v.y = fmaxf(v.y + __ldg(&bias[M0 + cc + 1]), 0.f);
        v.z = fmaxf(v.z + __ldg(&bias[M0 + cc + 2]), 0.f);
        v.w = fmaxf(v.w + __ldg(&bias[M0 + cc + 3]), 0.f);
        *reinterpret_cast<float4*>(outp + (bq + pos) * Cout + M0 + cc) = v;
    }
}

// ---------------- pool1: g_c1 (34^3 pos-major) -> d_out l1 (fp32) + g_l1h (fp16) ----------------
__global__ __launch_bounds__(128) void pool1_kernel(float* __restrict__ dout) {
    int pp = blockIdx.x;
    int b = blockIdx.z;
    int P0 = pp >> 8, P1 = (pp >> 4) & 15, P2 = pp & 15;
    int co4 = threadIdx.x << 2;

    float4 m = make_float4(-1e30f, -1e30f, -1e30f, -1e30f);
#pragma unroll
    for (int a = 0; a < 8; a++) {
        int c = (2 * P0 + (a >> 2) + 1) * (SP1 * SP1) + (2 * P1 + ((a >> 1) & 1) + 1) * SP1 + (2 * P2 + (a & 1) + 1);
        float4 v = *reinterpret_cast<const float4*>(&g_c1[((long)b * NPAD1 + c) * C1 + co4]);
        m.x = fmaxf(m.x, v.x); m.y = fmaxf(m.y, v.y); m.z = fmaxf(m.z, v.z); m.w = fmaxf(m.w, v.w);
    }
    int pad2 = (P0 + 1) * (SP2 * SP2) + (P1 + 1) * SP2 + (P2 + 1);
    __half2* lh = reinterpret_cast<__half2*>(&g_l1h[((long)b * NPAD2 + pad2) * C1 + co4]);
    lh[0] = __floats2half2_rn(m.x, m.y);
    lh[1] = __floats2half2_rn(m.z, m.w);

    long ob = ((long)b * 1024 + co4) * 4096 + pp;
    dout[ob] = m.x; dout[ob + 4096] = m.y; dout[ob + 2 * 4096] = m.z; dout[ob + 3 * 4096] = m.w;
}

// ---------------- pool2: g_c2 (18^3 pos-major) -> g_l2 (chan-major 8^3) ----------------
__global__ __launch_bounds__(256) void pool2_kernel() {
    int pp = blockIdx.x;
    int b = blockIdx.z;
    int Q0 = pp >> 6, Q1 = (pp >> 3) & 7, Q2 = pp & 7;
    int co4 = threadIdx.x << 2;

    float4 m = make_float4(-1e30f, -1e30f, -1e30f, -1e30f);
#pragma unroll
    for (int a = 0; a < 8; a++) {
        int c = (2 * Q0 + (a >> 2) + 1) * (SP2 * SP2) + (2 * Q1 + ((a >> 1) & 1) + 1) * SP2 + (2 * Q2 + (a & 1) + 1);
        float4 v = *reinterpret_cast<const float4*>(&g_c2[((long)b * NPAD2 + c) * C2 + co4]);
        m.x = fmaxf(m.x, v.x); m.y = fmaxf(m.y, v.y); m.z = fmaxf(m.z, v.z); m.w = fmaxf(m.w, v.w);
    }
    long ob = ((long)b * 1024 + co4) * 512 + pp;
    g_l2[ob] = m.x; g_l2[ob + 512] = m.y; g_l2[ob + 2 * 512] = m.z; g_l2[ob + 3 * 512] = m.w;
}

// ---------------- convT: 8 parity GEMMs (FFMA) ----------------
__global__ __launch_bounds__(256) void convt_kernel(const float* __restrict__ bt, float* __restrict__ out) {
    __shared__ float w_sh[32 * 128];
    __shared__ float x_sh[32 * 64];
    int posT = blockIdx.x;
    int coT  = blockIdx.y;
    int bp   = blockIdx.z;
    int b = bp >> 3, par = bp & 7;
    int tid = threadIdx.x;
    int col = tid & 31, prow = tid >> 5;

    const float* wbase = g_WtT + (long)par * (1024 * 512);
    const float* xbase = g_l2 + (long)b * (C2 * 512);

    float acc[4][8];
#pragma unroll
    for (int jc = 0; jc < 4; jc++)
#pragma unroll
        for (int jp = 0; jp < 8; jp++) acc[jc][jp] = 0.0f;

    for (int ci0 = 0; ci0 < 1024; ci0 += 32) {
        __syncthreads();
        for (int idx = tid; idx < 32 * 128; idx += 256) {
            int k = idx >> 7, c = idx & 127;
            w_sh[idx] = wbase[(long)(ci0 + k) * 512 + coT * 128 + c];
        }
        for (int idx = tid; idx < 32 * 64; idx += 256) {
            int k = idx >> 6, p = idx & 63;
            x_sh[idx] = xbase[(long)(ci0 + k) * 512 + posT * 64 + p];
        }
        __syncthreads();
#pragma unroll 4
        for (int k = 0; k < 32; k++) {
            float xv[8], wv[4];
#pragma unroll
            for (int jp = 0; jp < 8; jp++) xv[jp] = x_sh[k * 64 + prow + 8 * jp];
#pragma unroll
            for (int jc = 0; jc < 4; jc++) wv[jc] = w_sh[k * 128 + col + 32 * jc];
#pragma unroll
            for (int jc = 0; jc < 4; jc++)
#pragma unroll
                for (int jp = 0; jp < 8; jp++) acc[jc][jp] = fmaf(wv[jc], xv[jp], acc[jc][jp]);
        }
    }

    int az = par >> 2, ay = (par >> 1) & 1, ax = par & 1;
#pragma unroll
    for (int jc = 0; jc < 4; jc++) {
        int co = coT * 128 + col + 32 * jc;
        float bv = __ldg(&bt[co]);
#pragma unroll
        for (int jp = 0; jp < 8; jp++) {
            int pos = posT * 64 + prow + 8 * jp;
            int iz = pos >> 6, iy = (pos >> 3) & 7, ix = pos & 7;
            int s = (2 * iz + az) * 256 + (2 * iy + ay) * 16 + (2 * ix + ax);
            out[((long)b * 1024 + 512 + co) * 4096 + s] = acc[jc][jp] + bv;
        }
    }
}

// ---------------- launcher ----------------
extern "C" void kernel_launch(void* const* d_in, const int* in_sizes, int n_in,
                              void* d_out, int out_size)
{
    const float* pc  = (const float*)d_in[0];
    const float* W1  = (const float*)d_in[1];
    const float* b1  = (const float*)d_in[2];
    const float* W2  = (const float*)d_in[3];
    const float* b2  = (const float*)d_in[4];
    const float* Wc1 = (const float*)d_in[5];
    const float* bc1 = (const float*)d_in[6];
    const float* Wc2 = (const float*)d_in[7];
    const float* bc2 = (const float*)d_in[8];
    const float* Wt  = (const float*)d_in[9];
    const float* bt  = (const float*)d_in[10];
    float* out = (float*)d_out;

    void *p_xpad, *p_xh, *p_wk1, *p_wk2, *p_c1, *p_l1h, *p_c2;
    cudaGetSymbolAddress(&p_xpad, g_xpad);
    cudaGetSymbolAddress(&p_xh, g_xh);
    cudaGetSymbolAddress(&p_wk1, g_wk1);
    cudaGetSymbolAddress(&p_wk2, g_wk2);
    cudaGetSymbolAddress(&p_c1, g_c1);
    cudaGetSymbolAddress(&p_l1h, g_l1h);
    cudaGetSymbolAddress(&p_c2, g_c2);

    const int smem_pf = (128 * 257 + 128 * 65) * 4;   // 164,864 B
    const int smem_gm = 128 * DST * 4;                // 67,584 B (mainloop needs 59,136)
    cudaFuncSetAttribute(point_f_scatter_kernel, cudaFuncAttributeMaxDynamicSharedMemorySize, smem_pf);
    cudaFuncSetAttribute(gemm_conv_halo, cudaFuncAttributeMaxDynamicSharedMemorySize, smem_gm);

    // 1. zero scatter targets (replay-safe)
    zero_scratch_kernel<<<2048, 256>>>();
    // 2. weight transposes
    wt_transpose_kernel<<<(8 * 1024 * 512 + 255) / 256, 256>>>(Wt);
    wk_transpose_kernel<<<4096, 256>>>(Wc1, (__half*)p_wk1, C1, C0);
    wk_transpose_kernel<<<8192, 256>>>(Wc2, (__half*)p_wk2, C2, C1);
    // 3. point MLP + scatter
    point_h_kernel<<<TOTPTS / 8, 256>>>(pc, W1, b1);
    point_f_scatter_kernel<<<TOTPTS / 64, 256, smem_pf>>>(W2, b2);
    pack_half_kernel<<<2048, 256>>>((const float*)p_xpad, (__half*)p_xh, (long)(BATCH * NPAD1 * C0) / 4);
    // 4. conv1: halo-tiled fp16 mma (tiles 4x8x8 = 256, co-tiles 4)
    gemm_conv_halo<<<dim3(256, 4, BATCH), 256, smem_gm>>>(
        (const __half*)p_wk1, (const __half*)p_xh, bc1, (float*)p_c1,
        C0, C0 / 16, SP1, C1, 4, 8);
    // 5. pool1 -> d_out[:,0:512,:] + g_l1h
    pool1_kernel<<<dim3(4096, 1, BATCH), 128>>>(out);
    // 6. conv2: halo-tiled fp16 mma (tiles 2x4x4 = 32, co-tiles 8)
    gemm_conv_halo<<<dim3(32, 8, BATCH), 256, smem_gm>>>(
        (const __half*)p_wk2, (const __half*)p_l1h, bc2, (float*)p_c2,
        C1, C1 / 16, SP2, C2, 2, 4);
    // 7. pool2 -> g_l2
    pool2_kernel<<<dim3(512, 1, BATCH), 256>>>();
    // 8. convT -> d_out[:,512:1024,:]
    convt_kernel<<<dim3(8, 4, 16), 256>>>(bt, out);
}

// round 12
// speedup vs baseline: 1.4166x; 1.1644x over previous
#include <cuda_runtime.h>
#include <cuda_fp16.h>
#include <cstdint>

// ---------------- problem constants ----------------
#define BATCH 2
#define NPTS 100000
#define TOTPTS (BATCH * NPTS)
#define C0 256
#define C1 512
#define C2 1024
#define SP1 34                 // padded 32+2
#define NPAD1 (SP1*SP1*SP1)    // 39304
#define SP2 18                 // padded 16+2
#define NPAD2 (SP2*SP2*SP2)    // 5832
#define DST 132                // epilogue smem row stride (floats)
// halo-conv staging geometry (tile 8x(4)y(4)z, halo 10x6x6=360 rows)
#define AROW 48                // A smem row stride bytes (32B data + 16 pad)
#define BROW 48                // B smem row stride bytes
#define A_STAGE 6144           // 128*AROW
#define B_BUF_OFF 24576        // 4*A_STAGE
#define B_BUF 17280            // 360*BROW
// point_f mma staging
#define PFST 272               // row stride bytes (256B data + 16 pad)
#define PF_B_OFF 34816         // 128*PFST
#define PF_BASE_OFF 52224      // 34816 + 64*PFST
#define PF_SMEM 52736          // + 64*8

// ---------------- device scratch ----------------
__device__ float  g_xpad[BATCH * NPAD1 * C0];    // fp32 scatter grid (atomics)
__device__ __half g_xh[BATCH * NPAD1 * C0];      // fp16 conv1 input
__device__ __half g_hh[TOTPTS * 128];            // point hidden fp16
__device__ __half g_w2h[256 * 128];              // W2 fp16
__device__ int    g_flat[TOTPTS];                // padded voxel index
__device__ __half g_wk1[27 * C1 * C0];           // conv1 W [k][co][ci] fp16
__device__ __half g_wk2[27 * C2 * C1];           // conv2 W [k][co][ci] fp16
__device__ float  g_c1[BATCH * NPAD1 * C1];      // conv1 pre-pool pos-major fp32
__device__ __half g_l1h[BATCH * NPAD2 * C1];     // pooled l1, pos-major fp16
__device__ float  g_c2[BATCH * NPAD2 * C2];      // conv2 pre-pool pos-major fp32
__device__ float  g_l2[BATCH * C2 * 512];        // pooled l2, chan-major
__device__ float  g_WtT[8 * 1024 * 512];         // convT W (par,ci,co)

// ---------------- helpers ----------------
__device__ __forceinline__ uint32_t smem_u32p(const void* p) {
    uint32_t a;
    asm("{ .reg .u64 t; cvta.to.shared.u64 t, %1; cvt.u32.u64 %0, t; }" : "=r"(a) : "l"(p));
    return a;
}
__device__ __forceinline__ void mma_f16(float* c, const uint32_t* a, const uint32_t* b) {
    asm volatile(
        "mma.sync.aligned.m16n8k16.row.col.f32.f16.f16.f32 "
        "{%0,%1,%2,%3}, {%4,%5,%6,%7}, {%8,%9}, {%0,%1,%2,%3};\n"
        : "+f"(c[0]), "+f"(c[1]), "+f"(c[2]), "+f"(c[3])
        : "r"(a[0]), "r"(a[1]), "r"(a[2]), "r"(a[3]), "r"(b[0]), "r"(b[1]));
}
#define LDSM_X4(r0, r1, r2, r3, addr) \
    asm volatile("ldmatrix.sync.aligned.m8n8.x4.shared.b16 {%0,%1,%2,%3}, [%4];" \
        : "=r"(r0), "=r"(r1), "=r"(r2), "=r"(r3) : "r"(addr))
#define CP_ASYNC16(sa, ga) \
    asm volatile("cp.async.cg.shared.global [%0], [%1], 16;" :: "r"(sa), "l"(ga) : "memory")
#define CP_COMMIT() asm volatile("cp.async.commit_group;" ::: "memory")
#define CP_WAIT2()  asm volatile("cp.async.wait_group 2;" ::: "memory")
#define CP_WAITALL() asm volatile("cp.async.wait_all;" ::: "memory")

// ---------------- zero scratch (replay-safe) ----------------
__global__ void zero_scratch_kernel() {
    float4* p1 = reinterpret_cast<float4*>(g_xpad);
    int n1 = (BATCH * NPAD1 * C0) / 4;
    for (int i = blockIdx.x * blockDim.x + threadIdx.x; i < n1; i += gridDim.x * blockDim.x)
        p1[i] = make_float4(0.f, 0.f, 0.f, 0.f);
    float4* p2 = reinterpret_cast<float4*>(g_l1h);
    int n2 = (BATCH * NPAD2 * C1) / 8;
    for (int i = blockIdx.x * blockDim.x + threadIdx.x; i < n2; i += gridDim.x * blockDim.x)
        p2[i] = make_float4(0.f, 0.f, 0.f, 0.f);
}

// ---------------- pack fp32 grid -> fp16 ----------------
__global__ void pack_half_kernel(const float* __restrict__ src, __half* __restrict__ dst, long n4) {
    for (long i = (long)blockIdx.x * blockDim.x + threadIdx.x; i < n4; i += (long)gridDim.x * blockDim.x) {
        float4 v = reinterpret_cast<const float4*>(src)[i];
        __half2* d = reinterpret_cast<__half2*>(dst) + 2 * i;
        d[0] = __floats2half2_rn(v.x, v.y);
        d[1] = __floats2half2_rn(v.z, v.w);
    }
}

// ---------------- W2 -> fp16 ----------------
__global__ void w2_half_kernel(const float* __restrict__ W2) {
    int i = blockIdx.x * blockDim.x + threadIdx.x;
    if (i < 256 * 128) g_w2h[i] = __float2half_rn(W2[i]);
}

// ---------------- conv weight transpose [co][ci][27] -> [k][co][ci] fp16 ----------------
__global__ void wk_transpose_kernel(const float* __restrict__ w, __half* __restrict__ wk, int Cout, int Cin) {
    long total = (long)27 * Cout * Cin;
    for (long i = (long)blockIdx.x * blockDim.x + threadIdx.x; i < total; i += (long)gridDim.x * blockDim.x) {
        int ci = (int)(i % Cin);
        long r = i / Cin;
        int co = (int)(r % Cout);
        int k  = (int)(r / Cout);
        wk[i] = __float2half_rn(w[((long)co * Cin + ci) * 27 + k]);
    }
}

// ---------------- convT weight transpose (1024,512,2,2,2) -> (par,ci,co) ----------------
__global__ void wt_transpose_kernel(const float* __restrict__ Wt) {
    int i = blockIdx.x * blockDim.x + threadIdx.x;
    if (i >= 8 * 1024 * 512) return;
    int co = i & 511;
    int ci = (i >> 9) & 1023;
    int par = i >> 19;
    g_WtT[i] = Wt[ci * 4096 + co * 8 + par];
}

// ---------------- point MLP stage 1 (fp16 h out) ----------------
__global__ __launch_bounds__(256) void point_h_kernel(
    const float* __restrict__ pc, const float* __restrict__ W1, const float* __restrict__ b1)
{
    __shared__ float W1s[384];
    __shared__ float b1s[128];
    int tid = threadIdx.x;
    for (int i = tid; i < 384; i += 256) W1s[i] = W1[i];
    if (tid < 128) b1s[tid] = b1[tid];
    __syncthreads();

    int P = blockIdx.x * 8 + (tid >> 5);
    int lane = tid & 31;
    if (P >= TOTPTS) return;

    float x = pc[P * 3 + 0], y = pc[P * 3 + 1], z = pc[P * 3 + 2];
    int ix = (int)floorf((x + 1.0f) * 16.0f);
    int iy = (int)floorf((y + 1.0f) * 16.0f);
    int iz = (int)floorf((z + 1.0f) * 16.0f);
    float xcx = x - (ix * 0.0625f + 0.03125f - 1.0f);
    float xcy = y - (iy * 0.0625f + 0.03125f - 1.0f);
    float xcz = z - (iz * 0.0625f + 0.03125f - 1.0f);

    if (lane == 0) g_flat[P] = (ix + 1) * (SP1 * SP1) + (iy + 1) * SP1 + (iz + 1);

    __half* hrow = g_hh + (long)P * 128;
#pragma unroll
    for (int j = 0; j < 4; j++) {
        int o = lane + 32 * j;
        float v = W1s[o * 3 + 0] * xcx + W1s[o * 3 + 1] * xcy + W1s[o * 3 + 2] * xcz + b1s[o];
        hrow[o] = __float2half_rn(fmaxf(v, 0.0f));
    }
}

// ---------------- point MLP stage 2: fp16 mma + scatter-max ----------------
// CTA: 64 points x 128 couts (blockIdx.y half), K=128 single-shot.
__global__ __launch_bounds__(256) void point_f_mma_kernel(const float* __restrict__ b2) {
    extern __shared__ char pfs[];
    uint32_t sbase = smem_u32p(pfs);
    uint32_t Ab = sbase, Bb = sbase + PF_B_OFF;
    long* bases = reinterpret_cast<long*>(pfs + PF_BASE_OFF);

    int tid = threadIdx.x;
    int lane = tid & 31, wid = tid >> 5;
    int wm = wid >> 2, wn = wid & 3;
    int P0 = blockIdx.x * 64;
    int co0 = blockIdx.y << 7;

    // stage A = W2h tile [128 co][128 k], B = h tile [64 pt][128 k]
    {
        const __half* w2 = g_w2h + (long)co0 * 128;
        for (int idx = tid; idx < 2048; idx += 256) {      // 128 rows x 16 seg
            int r = idx >> 4, s = idx & 15;
            CP_ASYNC16(Ab + (uint32_t)r * PFST + (s << 4), w2 + r * 128 + s * 8);
        }
        const __half* hsrc = g_hh + (long)P0 * 128;
        for (int idx = tid; idx < 1024; idx += 256) {      // 64 rows x 16 seg
            int r = idx >> 4, s = idx & 15;
            CP_ASYNC16(Bb + (uint32_t)r * PFST + (s << 4), hsrc + r * 128 + s * 8);
        }
        CP_COMMIT();
        if (tid < 64) {
            int P = P0 + tid;
            bases[tid] = ((long)(P / NPTS) * NPAD1 + g_flat[P]) * C0;
        }
        CP_WAITALL();
        __syncthreads();
    }

    uint32_t ofsA[4];
#pragma unroll
    for (int fm = 0; fm < 4; fm++)
        ofsA[fm] = (uint32_t)(((wm << 6) + (fm << 4) + (lane & 15)) * PFST + ((lane >> 4) << 4));
    uint32_t ofsB = (uint32_t)(((wn << 4) + (lane & 7) + ((lane >> 4) << 3)) * PFST
                   + (((lane >> 3) & 1) << 4));

    float acc[4][2][4];
#pragma unroll
    for (int fm = 0; fm < 4; fm++)
#pragma unroll
        for (int fn = 0; fn < 2; fn++)
#pragma unroll
            for (int r = 0; r < 4; r++) acc[fm][fn][r] = 0.0f;

#pragma unroll
    for (int ks = 0; ks < 8; ks++) {
        uint32_t ko = (uint32_t)(ks << 5);
        uint32_t af[4][4], bf[4];
#pragma unroll
        for (int fm = 0; fm < 4; fm++)
            LDSM_X4(af[fm][0], af[fm][1], af[fm][2], af[fm][3], Ab + ofsA[fm] + ko);
        LDSM_X4(bf[0], bf[1], bf[2], bf[3], Bb + ofsB + ko);
#pragma unroll
        for (int fm = 0; fm < 4; fm++)
#pragma unroll
            for (int fn = 0; fn < 2; fn++)
                mma_f16(acc[fm][fn], af[fm], &bf[fn << 1]);
    }

    // scatter: D[m][n] -> atomicMax(grid[base(n) + co0 + m])
    int g = lane >> 2, t = lane & 3;
    int* gx = reinterpret_cast<int*>(g_xpad);
#pragma unroll
    for (int fm = 0; fm < 4; fm++) {
        int m0 = (wm << 6) + (fm << 4) + g;
        float bv0 = __ldg(&b2[co0 + m0]);
        float bv1 = __ldg(&b2[co0 + m0 + 8]);
#pragma unroll
        for (int fn = 0; fn < 2; fn++) {
            int n0 = (wn << 4) + (fn << 3) + (t << 1);
            long ba0 = bases[n0] + co0, ba1 = bases[n0 + 1] + co0;
            float f;
            f = acc[fm][fn][0] + bv0; if (f > 0.f) atomicMax(&gx[ba0 + m0], __float_as_int(f));
            f = acc[fm][fn][1] + bv0; if (f > 0.f) atomicMax(&gx[ba1 + m0], __float_as_int(f));
            f = acc[fm][fn][2] + bv1; if (f > 0.f) atomicMax(&gx[ba0 + m0 + 8], __float_as_int(f));
            f = acc[fm][fn][3] + bv1; if (f > 0.f) atomicMax(&gx[ba1 + m0 + 8], __float_as_int(f));
        }
    }
}

// ---------------- fp16 mma halo-tiled conv3x3x3 (+bias+relu) ----------------
__global__ __launch_bounds__(256, 2) void gemm_conv_halo(
    const __half* __restrict__ wk, const __half* __restrict__ xp,
    const float* __restrict__ bias, float* __restrict__ outp,
    int Cin, int nChunks, int Sp, int Cout, int ntx, int nty)
{
    extern __shared__ float sh[];
    uint32_t sbase = smem_u32p(sh);
    int tid = threadIdx.x;
    int lane = tid & 31, wid = tid >> 5;
    int wm = wid >> 2, wn = wid & 3;

    int t = blockIdx.x;
    int tix = t % ntx; int tr = t / ntx; int tiy = tr % nty; int tiz = tr / nty;
    int px0 = 1 + tix * 8, py0 = 1 + tiy * 4, pz0 = 1 + tiz * 4;
    int SPsq = Sp * Sp;
    long bq = (long)blockIdx.z * (Sp * SPsq);
    int M0 = blockIdx.y << 7;
    int posBase = pz0 * SPsq + py0 * Sp + px0;
    long row0 = (long)(pz0 - 1) * SPsq + (long)(py0 - 1) * Sp + (px0 - 1);
    int total = nChunks * 27;

    uint32_t ofsA[4];
#pragma unroll
    for (int fm = 0; fm < 4; fm++)
        ofsA[fm] = (uint32_t)(((wm << 6) + (fm << 4) + (lane & 15)) * AROW + ((lane >> 4) << 4));
    uint32_t hofs[2];
    uint32_t kbyte = (uint32_t)(((lane >> 3) & 1) << 4);
#pragma unroll
    for (int j = 0; j < 2; j++) {
        int n = (wn << 5) + (j << 4) + (lane & 7) + ((lane >> 4) << 3);
        int nx = n & 7, ny = (n >> 3) & 3, nz = n >> 5;
        hofs[j] = (uint32_t)((nz * 60 + ny * 10 + nx) * BROW) + kbyte;
    }

    float acc[4][4][4];
#pragma unroll
    for (int fm = 0; fm < 4; fm++)
#pragma unroll
        for (int fn = 0; fn < 4; fn++)
#pragma unroll
            for (int r = 0; r < 4; r++) acc[fm][fn][r] = 0.0f;

    int rowA = tid >> 1, segA = tid & 1;

    auto issue_stage = [&](int sIdx, int c, int tap, bool withB, int cb) {
        uint32_t stA = sbase + (uint32_t)sIdx * A_STAGE;
        const __half* ga = wk + ((long)tap * Cout + M0 + rowA) * Cin + (c << 4) + (segA << 3);
        CP_ASYNC16(stA + (uint32_t)rowA * AROW + (segA << 4), ga);
        if (withB) {
            uint32_t stB = sbase + B_BUF_OFF + (uint32_t)(cb & 1) * B_BUF;
            for (int s = tid; s < 720; s += 256) {
                int hr = s >> 1, hseg = s & 1;
                int hz = hr / 60; int h2 = hr - hz * 60;
                int hy = h2 / 10; int hx = h2 - hy * 10;
                long gpos = row0 + (long)hz * SPsq + hy * Sp + hx;
                const __half* gb = xp + (bq + gpos) * Cin + (cb << 4) + (hseg << 3);
                CP_ASYNC16(stB + (uint32_t)hr * BROW + (hseg << 4), gb);
            }
        }
        CP_COMMIT();
    };

    issue_stage(0, 0, 0, true, 0);
    issue_stage(1, 0, 1, false, 0);
    issue_stage(2, 0, 2, false, 0);

    int cI = 0, tapI = 3;
    int cU = 0, dxU = 0, dyU = 0, dzU = 0;

    for (int u = 0; u < total; u++) {
        CP_WAIT2();
        __syncthreads();
        if (u + 3 < total) {
            bool wB = (tapI == 24) && (cI + 1 < nChunks);
            issue_stage((u + 3) & 3, cI, tapI, wB, cI + 1);
            if (++tapI == 27) { tapI = 0; cI++; }
        } else CP_COMMIT();

        uint32_t stA = sbase + (uint32_t)(u & 3) * A_STAGE;
        uint32_t stB = sbase + B_BUF_OFF + (uint32_t)(cU & 1) * B_BUF
                     + (uint32_t)((dzU * 60 + dyU * 10 + dxU) * BROW);
        uint32_t af[4][4], bf[2][4];
#pragma unroll
        for (int fm = 0; fm < 4; fm++)
            LDSM_X4(af[fm][0], af[fm][1], af[fm][2], af[fm][3], stA + ofsA[fm]);
#pragma unroll
        for (int j = 0; j < 2; j++)
            LDSM_X4(bf[j][0], bf[j][1], bf[j][2], bf[j][3], stB + hofs[j]);
#pragma unroll
        for (int fm = 0; fm < 4; fm++)
#pragma unroll
            for (int fn = 0; fn < 4; fn++)
                mma_f16(acc[fm][fn], af[fm], &bf[fn >> 1][(fn & 1) << 1]);

        if (++dxU == 3) { dxU = 0; if (++dyU == 3) { dyU = 0; if (++dzU == 3) { dzU = 0; cU++; } } }
    }
    CP_WAITALL();

    __syncthreads();
    float* Dsh = sh;
    int g = lane >> 2, tq = lane & 3;
#pragma unroll
    for (int fm = 0; fm < 4; fm++) {
        int m = (wm << 6) + (fm << 4) + g;
#pragma unroll
        for (int fn = 0; fn < 4; fn++) {
            int n = (wn << 5) + (fn << 3) + (tq << 1);
            Dsh[n * DST + m]           = acc[fm][fn][0];
            Dsh[(n + 1) * DST + m]     = acc[fm][fn][1];
            Dsh[n * DST + m + 8]       = acc[fm][fn][2];
            Dsh[(n + 1) * DST + m + 8] = acc[fm][fn][3];
        }
    }
    __syncthreads();
    for (int i = tid; i < 4096; i += 256) {
        int n = i >> 5, cc = (i & 31) << 2;
        int nx = n & 7, ny = (n >> 3) & 3, nz = n >> 5;
        long pos = posBase + (long)nz * SPsq + ny * Sp + nx;
        float4 v = *reinterpret_cast<float4*>(&Dsh[n * DST + cc]);
        v.x = fmaxf(v.x + __ldg(&bias[M0 + cc + 0]), 0.f);
        v.y = fmaxf(v.y + __ldg(&bias[M0 + cc + 1]), 0.f);
        v.z = fmaxf(v.z + __ldg(&bias[M0 + cc + 2]), 0.f);
        v.w = fmaxf(v.w + __ldg(&bias[M0 + cc + 3]), 0.f);
        *reinterpret_cast<float4*>(outp + (bq + pos) * Cout + M0 + cc) = v;
    }
}

// ---------------- pool1: g_c1 -> d_out l1 (fp32) + g_l1h (fp16) ----------------
__global__ __launch_bounds__(128) void pool1_kernel(float* __restrict__ dout) {
    int pp = blockIdx.x;
    int b = blockIdx.z;
    int P0 = pp >> 8, P1 = (pp >> 4) & 15, P2 = pp & 15;
    int co4 = threadIdx.x << 2;

    float4 m = make_float4(-1e30f, -1e30f, -1e30f, -1e30f);
#pragma unroll
    for (int a = 0; a < 8; a++) {
        int c = (2 * P0 + (a >> 2) + 1) * (SP1 * SP1) + (2 * P1 + ((a >> 1) & 1) + 1) * SP1 + (2 * P2 + (a & 1) + 1);
        float4 v = *reinterpret_cast<const float4*>(&g_c1[((long)b * NPAD1 + c) * C1 + co4]);
        m.x = fmaxf(m.x, v.x); m.y = fmaxf(m.y, v.y); m.z = fmaxf(m.z, v.z); m.w = fmaxf(m.w, v.w);
    }
    int pad2 = (P0 + 1) * (SP2 * SP2) + (P1 + 1) * SP2 + (P2 + 1);
    __half2* lh = reinterpret_cast<__half2*>(&g_l1h[((long)b * NPAD2 + pad2) * C1 + co4]);
    lh[0] = __floats2half2_rn(m.x, m.y);
    lh[1] = __floats2half2_rn(m.z, m.w);

    long ob = ((long)b * 1024 + co4) * 4096 + pp;
    dout[ob] = m.x; dout[ob + 4096] = m.y; dout[ob + 2 * 4096] = m.z; dout[ob + 3 * 4096] = m.w;
}

// ---------------- pool2: g_c2 -> g_l2 (chan-major 8^3) ----------------
__global__ __launch_bounds__(256) void pool2_kernel() {
    int pp = blockIdx.x;
    int b = blockIdx.z;
    int Q0 = pp >> 6, Q1 = (pp >> 3) & 7, Q2 = pp & 7;
    int co4 = threadIdx.x << 2;

    float4 m = make_float4(-1e30f, -1e30f, -1e30f, -1e30f);
#pragma unroll
    for (int a = 0; a < 8; a++) {
        int c = (2 * Q0 + (a >> 2) + 1) * (SP2 * SP2) + (2 * Q1 + ((a >> 1) & 1) + 1) * SP2 + (2 * Q2 + (a & 1) + 1);
        float4 v = *reinterpret_cast<const float4*>(&g_c2[((long)b * NPAD2 + c) * C2 + co4]);
        m.x = fmaxf(m.x, v.x); m.y = fmaxf(m.y, v.y); m.z = fmaxf(m.z, v.z); m.w = fmaxf(m.w, v.w);
    }
    long ob = ((long)b * 1024 + co4) * 512 + pp;
    g_l2[ob] = m.x; g_l2[ob + 512] = m.y; g_l2[ob + 2 * 512] = m.z; g_l2[ob + 3 * 512] = m.w;
}

// ---------------- convT: 8 parity GEMMs (FFMA) ----------------
__global__ __launch_bounds__(256) void convt_kernel(const float* __restrict__ bt, float* __restrict__ out) {
    __shared__ float w_sh[32 * 128];
    __shared__ float x_sh[32 * 64];
    int posT = blockIdx.x;
    int coT  = blockIdx.y;
    int bp   = blockIdx.z;
    int b = bp >> 3, par = bp & 7;
    int tid = threadIdx.x;
    int col = tid & 31, prow = tid >> 5;

    const float* wbase = g_WtT + (long)par * (1024 * 512);
    const float* xbase = g_l2 + (long)b * (C2 * 512);

    float acc[4][8];
#pragma unroll
    for (int jc = 0; jc < 4; jc++)
#pragma unroll
        for (int jp = 0; jp < 8; jp++) acc[jc][jp] = 0.0f;

    for (int ci0 = 0; ci0 < 1024; ci0 += 32) {
        __syncthreads();
        for (int idx = tid; idx < 32 * 128; idx += 256) {
            int k = idx >> 7, c = idx & 127;
            w_sh[idx] = wbase[(long)(ci0 + k) * 512 + coT * 128 + c];
        }
        for (int idx = tid; idx < 32 * 64; idx += 256) {
            int k = idx >> 6, p = idx & 63;
            x_sh[idx] = xbase[(long)(ci0 + k) * 512 + posT * 64 + p];
        }
        __syncthreads();
#pragma unroll 4
        for (int k = 0; k < 32; k++) {
            float xv[8], wv[4];
#pragma unroll
            for (int jp = 0; jp < 8; jp++) xv[jp] = x_sh[k * 64 + prow + 8 * jp];
#pragma unroll
            for (int jc = 0; jc < 4; jc++) wv[jc] = w_sh[k * 128 + col + 32 * jc];
#pragma unroll
            for (int jc = 0; jc < 4; jc++)
#pragma unroll
                for (int jp = 0; jp < 8; jp++) acc[jc][jp] = fmaf(wv[jc], xv[jp], acc[jc][jp]);
        }
    }

    int az = par >> 2, ay = (par >> 1) & 1, ax = par & 1;
#pragma unroll
    for (int jc = 0; jc < 4; jc++) {
        int co = coT * 128 + col + 32 * jc;
        float bv = __ldg(&bt[co]);
#pragma unroll
        for (int jp = 0; jp < 8; jp++) {
            int pos = posT * 64 + prow + 8 * jp;
            int iz = pos >> 6, iy = (pos >> 3) & 7, ix = pos & 7;
            int s = (2 * iz + az) * 256 + (2 * iy + ay) * 16 + (2 * ix + ax);
            out[((long)b * 1024 + 512 + co) * 4096 + s] = acc[jc][jp] + bv;
        }
    }
}

// ---------------- launcher ----------------
extern "C" void kernel_launch(void* const* d_in, const int* in_sizes, int n_in,
                              void* d_out, int out_size)
{
    const float* pc  = (const float*)d_in[0];
    const float* W1  = (const float*)d_in[1];
    const float* b1  = (const float*)d_in[2];
    const float* W2  = (const float*)d_in[3];
    const float* b2  = (const float*)d_in[4];
    const float* Wc1 = (const float*)d_in[5];
    const float* bc1 = (const float*)d_in[6];
    const float* Wc2 = (const float*)d_in[7];
    const float* bc2 = (const float*)d_in[8];
    const float* Wt  = (const float*)d_in[9];
    const float* bt  = (const float*)d_in[10];
    float* out = (float*)d_out;

    void *p_xpad, *p_xh, *p_wk1, *p_wk2, *p_c1, *p_l1h, *p_c2;
    cudaGetSymbolAddress(&p_xpad, g_xpad);
    cudaGetSymbolAddress(&p_xh, g_xh);
    cudaGetSymbolAddress(&p_wk1, g_wk1);
    cudaGetSymbolAddress(&p_wk2, g_wk2);
    cudaGetSymbolAddress(&p_c1, g_c1);
    cudaGetSymbolAddress(&p_l1h, g_l1h);
    cudaGetSymbolAddress(&p_c2, g_c2);

    const int smem_gm = 128 * DST * 4;                // 67,584 B (mainloop needs 59,136)
    cudaFuncSetAttribute(gemm_conv_halo, cudaFuncAttributeMaxDynamicSharedMemorySize, smem_gm);
    cudaFuncSetAttribute(point_f_mma_kernel, cudaFuncAttributeMaxDynamicSharedMemorySize, PF_SMEM);

    // 1. zero scatter targets (replay-safe)
    zero_scratch_kernel<<<2048, 256>>>();
    // 2. weight conversions/transposes
    wt_transpose_kernel<<<(8 * 1024 * 512 + 255) / 256, 256>>>(Wt);
    wk_transpose_kernel<<<4096, 256>>>(Wc1, (__half*)p_wk1, C1, C0);
    wk_transpose_kernel<<<8192, 256>>>(Wc2, (__half*)p_wk2, C2, C1);
    w2_half_kernel<<<128, 256>>>(W2);
    // 3. point MLP + scatter (fp16 mma)
    point_h_kernel<<<TOTPTS / 8, 256>>>(pc, W1, b1);
    point_f_mma_kernel<<<dim3(TOTPTS / 64, 2), 256, PF_SMEM>>>(b2);
    pack_half_kernel<<<2048, 256>>>((const float*)p_xpad, (__half*)p_xh, (long)(BATCH * NPAD1 * C0) / 4);
    // 4. conv1: halo-tiled fp16 mma
    gemm_conv_halo<<<dim3(256, 4, BATCH), 256, smem_gm>>>(
        (const __half*)p_wk1, (const __half*)p_xh, bc1, (float*)p_c1,
        C0, C0 / 16, SP1, C1, 4, 8);
    // 5. pool1 -> d_out[:,0:512,:] + g_l1h
    pool1_kernel<<<dim3(4096, 1, BATCH), 128>>>(out);
    // 6. conv2: halo-tiled fp16 mma
    gemm_conv_halo<<<dim3(32, 8, BATCH), 256, smem_gm>>>(
        (const __half*)p_wk2, (const __half*)p_l1h, bc2, (float*)p_c2,
        C1, C1 / 16, SP2, C2, 2, 4);
    // 7. pool2 -> g_l2
    pool2_kernel<<<dim3(512, 1, BATCH), 256>>>();
    // 8. convT -> d_out[:,512:1024,:]
    convt_kernel<<<dim3(8, 4, 16), 256>>>(bt, out);
}

// round 13
// speedup vs baseline: 1.7348x; 1.2246x over previous
#include <cuda_runtime.h>
#include <cuda_fp16.h>
#include <cstdint>

// ---------------- problem constants ----------------
#define BATCH 2
#define NPTS 100000
#define TOTPTS (BATCH * NPTS)
#define C0 256
#define C1 512
#define C2 1024
#define SP1 34                 // padded 32+2
#define NPAD1 (SP1*SP1*SP1)    // 39304
#define SP2 18                 // padded 16+2
#define NPAD2 (SP2*SP2*SP2)    // 5832
#define DST 132                // epilogue smem row stride (floats)
// halo-conv staging geometry (tile 8x(4)y(4)z, halo 10x6x6=360 rows)
#define AROW 48
#define BROW 48
#define A_STAGE 6144           // 128*AROW
#define B_BUF_OFF 24576        // 4*A_STAGE
#define B_BUF 17280            // 360*BROW
// point_f mma staging
#define PFST 272
#define PF_B_OFF 34816
#define PF_BASE_OFF 52224
#define PF_SMEM 52736
// convT mma staging (R9-style 32-k chunks)
#define CSROW 80
#define CSTAGE 20480
#define CB_OFF 10240

// ---------------- device scratch ----------------
__device__ float  g_xpad[BATCH * NPAD1 * C0];    // fp32 scatter grid (atomics)
__device__ __half g_xh[BATCH * NPAD1 * C0];      // fp16 conv1 input
__device__ __half g_hh[TOTPTS * 128];            // point hidden fp16
__device__ __half g_w2h[256 * 128];              // W2 fp16
__device__ int    g_flat[TOTPTS];                // padded voxel index
__device__ __half g_wk1[27 * C1 * C0];           // conv1 W [k][co][ci] fp16
__device__ __half g_wk2[27 * C2 * C1];           // conv2 W [k][co][ci] fp16
__device__ __half g_l1h[BATCH * NPAD2 * C1];     // pooled l1, pos-major fp16 (zero ring)
__device__ __half g_l2h[BATCH * 512 * C2];       // pooled l2, pos-major fp16
__device__ __half g_wtTh[8 * 512 * 1024];        // convT W (par, co, ci) fp16

// ---------------- helpers ----------------
__device__ __forceinline__ uint32_t smem_u32p(const void* p) {
    uint32_t a;
    asm("{ .reg .u64 t; cvta.to.shared.u64 t, %1; cvt.u32.u64 %0, t; }" : "=r"(a) : "l"(p));
    return a;
}
__device__ __forceinline__ void mma_f16(float* c, const uint32_t* a, const uint32_t* b) {
    asm volatile(
        "mma.sync.aligned.m16n8k16.row.col.f32.f16.f16.f32 "
        "{%0,%1,%2,%3}, {%4,%5,%6,%7}, {%8,%9}, {%0,%1,%2,%3};\n"
        : "+f"(c[0]), "+f"(c[1]), "+f"(c[2]), "+f"(c[3])
        : "r"(a[0]), "r"(a[1]), "r"(a[2]), "r"(a[3]), "r"(b[0]), "r"(b[1]));
}
#define LDSM_X4(r0, r1, r2, r3, addr) \
    asm volatile("ldmatrix.sync.aligned.m8n8.x4.shared.b16 {%0,%1,%2,%3}, [%4];" \
        : "=r"(r0), "=r"(r1), "=r"(r2), "=r"(r3) : "r"(addr))
#define CP_ASYNC16(sa, ga) \
    asm volatile("cp.async.cg.shared.global [%0], [%1], 16;" :: "r"(sa), "l"(ga) : "memory")
#define CP_COMMIT() asm volatile("cp.async.commit_group;" ::: "memory")
#define CP_WAIT2()  asm volatile("cp.async.wait_group 2;" ::: "memory")
#define CP_WAITALL() asm volatile("cp.async.wait_all;" ::: "memory")

// ---------------- zero scratch (replay-safe) ----------------
__global__ void zero_scratch_kernel() {
    float4* p1 = reinterpret_cast<float4*>(g_xpad);
    int n1 = (BATCH * NPAD1 * C0) / 4;
    for (int i = blockIdx.x * blockDim.x + threadIdx.x; i < n1; i += gridDim.x * blockDim.x)
        p1[i] = make_float4(0.f, 0.f, 0.f, 0.f);
    float4* p2 = reinterpret_cast<float4*>(g_l1h);
    int n2 = (BATCH * NPAD2 * C1) / 8;
    for (int i = blockIdx.x * blockDim.x + threadIdx.x; i < n2; i += gridDim.x * blockDim.x)
        p2[i] = make_float4(0.f, 0.f, 0.f, 0.f);
}

// ---------------- pack fp32 grid -> fp16 ----------------
__global__ void pack_half_kernel(const float* __restrict__ src, __half* __restrict__ dst, long n4) {
    for (long i = (long)blockIdx.x * blockDim.x + threadIdx.x; i < n4; i += (long)gridDim.x * blockDim.x) {
        float4 v = reinterpret_cast<const float4*>(src)[i];
        __half2* d = reinterpret_cast<__half2*>(dst) + 2 * i;
        d[0] = __floats2half2_rn(v.x, v.y);
        d[1] = __floats2half2_rn(v.z, v.w);
    }
}

// ---------------- W2 -> fp16 ----------------
__global__ void w2_half_kernel(const float* __restrict__ W2) {
    int i = blockIdx.x * blockDim.x + threadIdx.x;
    if (i < 256 * 128) g_w2h[i] = __float2half_rn(W2[i]);
}

// ---------------- conv weight transpose [co][ci][27] -> [k][co][ci] fp16 ----------------
__global__ void wk_transpose_kernel(const float* __restrict__ w, __half* __restrict__ wk, int Cout, int Cin) {
    long total = (long)27 * Cout * Cin;
    for (long i = (long)blockIdx.x * blockDim.x + threadIdx.x; i < total; i += (long)gridDim.x * blockDim.x) {
        int ci = (int)(i % Cin);
        long r = i / Cin;
        int co = (int)(r % Cout);
        int k  = (int)(r / Cout);
        wk[i] = __float2half_rn(w[((long)co * Cin + ci) * 27 + k]);
    }
}

// ---------------- convT weight transpose (1024,512,2,2,2) -> (par,co,ci) fp16 ----------------
__global__ void wt_transpose_kernel(const float* __restrict__ Wt) {
    int i = blockIdx.x * blockDim.x + threadIdx.x;
    if (i >= 8 * 512 * 1024) return;
    int ci  = i & 1023;
    int co  = (i >> 10) & 511;
    int par = i >> 19;
    g_wtTh[i] = __float2half_rn(Wt[ci * 4096 + co * 8 + par]);
}

// ---------------- point MLP stage 1 (fp16 h out) ----------------
__global__ __launch_bounds__(256) void point_h_kernel(
    const float* __restrict__ pc, const float* __restrict__ W1, const float* __restrict__ b1)
{
    __shared__ float W1s[384];
    __shared__ float b1s[128];
    int tid = threadIdx.x;
    for (int i = tid; i < 384; i += 256) W1s[i] = W1[i];
    if (tid < 128) b1s[tid] = b1[tid];
    __syncthreads();

    int P = blockIdx.x * 8 + (tid >> 5);
    int lane = tid & 31;
    if (P >= TOTPTS) return;

    float x = pc[P * 3 + 0], y = pc[P * 3 + 1], z = pc[P * 3 + 2];
    int ix = (int)floorf((x + 1.0f) * 16.0f);
    int iy = (int)floorf((y + 1.0f) * 16.0f);
    int iz = (int)floorf((z + 1.0f) * 16.0f);
    float xcx = x - (ix * 0.0625f + 0.03125f - 1.0f);
    float xcy = y - (iy * 0.0625f + 0.03125f - 1.0f);
    float xcz = z - (iz * 0.0625f + 0.03125f - 1.0f);

    if (lane == 0) g_flat[P] = (ix + 1) * (SP1 * SP1) + (iy + 1) * SP1 + (iz + 1);

    __half* hrow = g_hh + (long)P * 128;
#pragma unroll
    for (int j = 0; j < 4; j++) {
        int o = lane + 32 * j;
        float v = W1s[o * 3 + 0] * xcx + W1s[o * 3 + 1] * xcy + W1s[o * 3 + 2] * xcz + b1s[o];
        hrow[o] = __float2half_rn(fmaxf(v, 0.0f));
    }
}

// ---------------- point MLP stage 2: fp16 mma + scatter-max ----------------
__global__ __launch_bounds__(256) void point_f_mma_kernel(const float* __restrict__ b2) {
    extern __shared__ char pfs[];
    uint32_t sbase = smem_u32p(pfs);
    uint32_t Ab = sbase, Bb = sbase + PF_B_OFF;
    long* bases = reinterpret_cast<long*>(pfs + PF_BASE_OFF);

    int tid = threadIdx.x;
    int lane = tid & 31, wid = tid >> 5;
    int wm = wid >> 2, wn = wid & 3;
    int P0 = blockIdx.x * 64;
    int co0 = blockIdx.y << 7;

    {
        const __half* w2 = g_w2h + (long)co0 * 128;
        for (int idx = tid; idx < 2048; idx += 256) {
            int r = idx >> 4, s = idx & 15;
            CP_ASYNC16(Ab + (uint32_t)r * PFST + (s << 4), w2 + r * 128 + s * 8);
        }
        const __half* hsrc = g_hh + (long)P0 * 128;
        for (int idx = tid; idx < 1024; idx += 256) {
            int r = idx >> 4, s = idx & 15;
            CP_ASYNC16(Bb + (uint32_t)r * PFST + (s << 4), hsrc + r * 128 + s * 8);
        }
        CP_COMMIT();
        if (tid < 64) {
            int P = P0 + tid;
            bases[tid] = ((long)(P / NPTS) * NPAD1 + g_flat[P]) * C0;
        }
        CP_WAITALL();
        __syncthreads();
    }

    uint32_t ofsA[4];
#pragma unroll
    for (int fm = 0; fm < 4; fm++)
        ofsA[fm] = (uint32_t)(((wm << 6) + (fm << 4) + (lane & 15)) * PFST + ((lane >> 4) << 4));
    uint32_t ofsB = (uint32_t)(((wn << 4) + (lane & 7) + ((lane >> 4) << 3)) * PFST
                   + (((lane >> 3) & 1) << 4));

    float acc[4][2][4];
#pragma unroll
    for (int fm = 0; fm < 4; fm++)
#pragma unroll
        for (int fn = 0; fn < 2; fn++)
#pragma unroll
            for (int r = 0; r < 4; r++) acc[fm][fn][r] = 0.0f;

#pragma unroll
    for (int ks = 0; ks < 8; ks++) {
        uint32_t ko = (uint32_t)(ks << 5);
        uint32_t af[4][4], bf[4];
#pragma unroll
        for (int fm = 0; fm < 4; fm++)
            LDSM_X4(af[fm][0], af[fm][1], af[fm][2], af[fm][3], Ab + ofsA[fm] + ko);
        LDSM_X4(bf[0], bf[1], bf[2], bf[3], Bb + ofsB + ko);
#pragma unroll
        for (int fm = 0; fm < 4; fm++)
#pragma unroll
            for (int fn = 0; fn < 2; fn++)
                mma_f16(acc[fm][fn], af[fm], &bf[fn << 1]);
    }

    int g = lane >> 2, t = lane & 3;
    int* gx = reinterpret_cast<int*>(g_xpad);
#pragma unroll
    for (int fm = 0; fm < 4; fm++) {
        int m0 = (wm << 6) + (fm << 4) + g;
        float bv0 = __ldg(&b2[co0 + m0]);
        float bv1 = __ldg(&b2[co0 + m0 + 8]);
#pragma unroll
        for (int fn = 0; fn < 2; fn++) {
            int n0 = (wn << 4) + (fn << 3) + (t << 1);
            long ba0 = bases[n0] + co0, ba1 = bases[n0 + 1] + co0;
            float f;
            f = acc[fm][fn][0] + bv0; if (f > 0.f) atomicMax(&gx[ba0 + m0], __float_as_int(f));
            f = acc[fm][fn][1] + bv0; if (f > 0.f) atomicMax(&gx[ba1 + m0], __float_as_int(f));
            f = acc[fm][fn][2] + bv1; if (f > 0.f) atomicMax(&gx[ba0 + m0 + 8], __float_as_int(f));
            f = acc[fm][fn][3] + bv1; if (f > 0.f) atomicMax(&gx[ba1 + m0 + 8], __float_as_int(f));
        }
    }
}

// ---------------- fp16 mma halo-tiled conv3x3x3 + FUSED bias/relu/maxpool ----------------
// mode 1: write d_out l1 (fp32 chan-major) + g_l1h (fp16 pos-major padded)
// mode 2: write g_l2h (fp16 pos-major 8^3)
__global__ __launch_bounds__(256, 2) void gemm_conv_halo(
    const __half* __restrict__ wk, const __half* __restrict__ xp,
    const float* __restrict__ bias, float* __restrict__ dout,
    int Cin, int nChunks, int Sp, int Cout, int ntx, int nty, int mode)
{
    extern __shared__ float sh[];
    uint32_t sbase = smem_u32p(sh);
    int tid = threadIdx.x;
    int lane = tid & 31, wid = tid >> 5;
    int wm = wid >> 2, wn = wid & 3;

    int t = blockIdx.x;
    int tix = t % ntx; int tr = t / ntx; int tiy = tr % nty; int tiz = tr / nty;
    int px0 = 1 + tix * 8, py0 = 1 + tiy * 4, pz0 = 1 + tiz * 4;
    int SPsq = Sp * Sp;
    int bz = blockIdx.z;
    long bq = (long)bz * (Sp * SPsq);
    int M0 = blockIdx.y << 7;
    long row0 = (long)(pz0 - 1) * SPsq + (long)(py0 - 1) * Sp + (px0 - 1);
    int total = nChunks * 27;

    uint32_t ofsA[4];
#pragma unroll
    for (int fm = 0; fm < 4; fm++)
        ofsA[fm] = (uint32_t)(((wm << 6) + (fm << 4) + (lane & 15)) * AROW + ((lane >> 4) << 4));
    uint32_t hofs[2];
    uint32_t kbyte = (uint32_t)(((lane >> 3) & 1) << 4);
#pragma unroll
    for (int j = 0; j < 2; j++) {
        int n = (wn << 5) + (j << 4) + (lane & 7) + ((lane >> 4) << 3);
        int nx = n & 7, ny = (n >> 3) & 3, nz = n >> 5;
        hofs[j] = (uint32_t)((nz * 60 + ny * 10 + nx) * BROW) + kbyte;
    }

    float acc[4][4][4];
#pragma unroll
    for (int fm = 0; fm < 4; fm++)
#pragma unroll
        for (int fn = 0; fn < 4; fn++)
#pragma unroll
            for (int r = 0; r < 4; r++) acc[fm][fn][r] = 0.0f;

    int rowA = tid >> 1, segA = tid & 1;

    auto issue_stage = [&](int sIdx, int c, int tap, bool withB, int cb) {
        uint32_t stA = sbase + (uint32_t)sIdx * A_STAGE;
        const __half* ga = wk + ((long)tap * Cout + M0 + rowA) * Cin + (c << 4) + (segA << 3);
        CP_ASYNC16(stA + (uint32_t)rowA * AROW + (segA << 4), ga);
        if (withB) {
            uint32_t stB = sbase + B_BUF_OFF + (uint32_t)(cb & 1) * B_BUF;
            for (int s = tid; s < 720; s += 256) {
                int hr = s >> 1, hseg = s & 1;
                int hz = hr / 60; int h2 = hr - hz * 60;
                int hy = h2 / 10; int hx = h2 - hy * 10;
                long gpos = row0 + (long)hz * SPsq + hy * Sp + hx;
                const __half* gb = xp + (bq + gpos) * Cin + (cb << 4) + (hseg << 3);
                CP_ASYNC16(stB + (uint32_t)hr * BROW + (hseg << 4), gb);
            }
        }
        CP_COMMIT();
    };

    issue_stage(0, 0, 0, true, 0);
    issue_stage(1, 0, 1, false, 0);
    issue_stage(2, 0, 2, false, 0);

    int cI = 0, tapI = 3;
    int cU = 0, dxU = 0, dyU = 0, dzU = 0;

    for (int u = 0; u < total; u++) {
        CP_WAIT2();
        __syncthreads();
        if (u + 3 < total) {
            bool wB = (tapI == 24) && (cI + 1 < nChunks);
            issue_stage((u + 3) & 3, cI, tapI, wB, cI + 1);
            if (++tapI == 27) { tapI = 0; cI++; }
        } else CP_COMMIT();

        uint32_t stA = sbase + (uint32_t)(u & 3) * A_STAGE;
        uint32_t stB = sbase + B_BUF_OFF + (uint32_t)(cU & 1) * B_BUF
                     + (uint32_t)((dzU * 60 + dyU * 10 + dxU) * BROW);
        uint32_t af[4][4], bf[2][4];
#pragma unroll
        for (int fm = 0; fm < 4; fm++)
            LDSM_X4(af[fm][0], af[fm][1], af[fm][2], af[fm][3], stA + ofsA[fm]);
#pragma unroll
        for (int j = 0; j < 2; j++)
            LDSM_X4(bf[j][0], bf[j][1], bf[j][2], bf[j][3], stB + hofs[j]);
#pragma unroll
        for (int fm = 0; fm < 4; fm++)
#pragma unroll
            for (int fn = 0; fn < 4; fn++)
                mma_f16(acc[fm][fn], af[fm], &bf[fn >> 1][(fn & 1) << 1]);

        if (++dxU == 3) { dxU = 0; if (++dyU == 3) { dyU = 0; if (++dzU == 3) { dzU = 0; cU++; } } }
    }
    CP_WAITALL();

    // -------- epilogue: transpose via smem, then FUSED 2x2x2 maxpool + bias + relu --------
    __syncthreads();
    float* Dsh = sh;
    int g = lane >> 2, tq = lane & 3;
#pragma unroll
    for (int fm = 0; fm < 4; fm++) {
        int m = (wm << 6) + (fm << 4) + g;
#pragma unroll
        for (int fn = 0; fn < 4; fn++) {
            int n = (wn << 5) + (fn << 3) + (tq << 1);
            Dsh[n * DST + m]           = acc[fm][fn][0];
            Dsh[(n + 1) * DST + m]     = acc[fm][fn][1];
            Dsh[n * DST + m + 8]       = acc[fm][fn][2];
            Dsh[(n + 1) * DST + m + 8] = acc[fm][fn][3];
        }
    }
    __syncthreads();
    // 16 pooled cells x 32 co-groups(4) = 512 items
    for (int i = tid; i < 512; i += 256) {
        int cc = (i & 31) << 2;
        int pcell = i >> 5;
        int jx = pcell & 3, jy = (pcell >> 2) & 1, jz = pcell >> 3;
        float4 m = make_float4(-1e30f, -1e30f, -1e30f, -1e30f);
#pragma unroll
        for (int d = 0; d < 8; d++) {
            int n = ((jz * 2 + (d >> 2)) << 5) + ((jy * 2 + ((d >> 1) & 1)) << 3) + (jx * 2 + (d & 1));
            float4 v = *reinterpret_cast<float4*>(&Dsh[n * DST + cc]);
            m.x = fmaxf(m.x, v.x); m.y = fmaxf(m.y, v.y); m.z = fmaxf(m.z, v.z); m.w = fmaxf(m.w, v.w);
        }
        m.x = fmaxf(m.x + __ldg(&bias[M0 + cc + 0]), 0.f);
        m.y = fmaxf(m.y + __ldg(&bias[M0 + cc + 1]), 0.f);
        m.z = fmaxf(m.z + __ldg(&bias[M0 + cc + 2]), 0.f);
        m.w = fmaxf(m.w + __ldg(&bias[M0 + cc + 3]), 0.f);
        int PX = (tix << 2) + jx, PY = (tiy << 1) + jy, PZ = (tiz << 1) + jz;
        if (mode == 1) {
            int s = PZ * 256 + PY * 16 + PX;
            long ob = ((long)bz * 1024 + M0 + cc) * 4096 + s;
            dout[ob] = m.x; dout[ob + 4096] = m.y; dout[ob + 2 * 4096] = m.z; dout[ob + 3 * 4096] = m.w;
            int pad2 = (PZ + 1) * (SP2 * SP2) + (PY + 1) * SP2 + (PX + 1);
            __half2* lh = reinterpret_cast<__half2*>(&g_l1h[((long)bz * NPAD2 + pad2) * C1 + M0 + cc]);
            lh[0] = __floats2half2_rn(m.x, m.y);
            lh[1] = __floats2half2_rn(m.z, m.w);
        } else {
            int pp = PZ * 64 + PY * 8 + PX;
            __half2* lh = reinterpret_cast<__half2*>(&g_l2h[((long)bz * 512 + pp) * C2 + M0 + cc]);
            lh[0] = __floats2half2_rn(m.x, m.y);
            lh[1] = __floats2half2_rn(m.z, m.w);
        }
    }
}

// ---------------- convT: fp16 mma parity GEMMs (R9-style chunked pipeline) ----------------
// CTA: 128 co x 128 pos, K=1024 in 32-k chunks. grid (posT 4, coT 4, b*8+par).
__global__ __launch_bounds__(256, 2) void convt_mma_kernel(
    const float* __restrict__ bt, float* __restrict__ out)
{
    extern __shared__ float sh[];
    uint32_t sbase = smem_u32p(sh);
    int tid = threadIdx.x;
    int lane = tid & 31, wid = tid >> 5;
    int wm = wid >> 2, wn = wid & 3;
    int posT = blockIdx.x, coT = blockIdx.y;
    int bp = blockIdx.z;
    int b = bp >> 3, par = bp & 7;

    const __half* A = g_wtTh + (long)par * (512 * 1024) + (long)(coT << 7) * 1024;
    const __half* B = g_l2h + (long)b * (512 * 1024) + (long)(posT << 7) * 1024;

    uint32_t ofsA[4], ofsB[2];
#pragma unroll
    for (int fm = 0; fm < 4; fm++)
        ofsA[fm] = (uint32_t)(((wm << 6) + (fm << 4) + (lane & 15)) * CSROW + ((lane >> 4) << 4));
#pragma unroll
    for (int j = 0; j < 2; j++) {
        int row = (wn << 5) + (j << 4) + (lane & 7) + ((lane >> 4) << 3);
        ofsB[j] = (uint32_t)(CB_OFF + row * CSROW + (((lane >> 3) & 1) << 4));
    }

    float acc[4][4][4];
#pragma unroll
    for (int fm = 0; fm < 4; fm++)
#pragma unroll
        for (int fn = 0; fn < 4; fn++)
#pragma unroll
            for (int r = 0; r < 4; r++) acc[fm][fn][r] = 0.0f;

    int rowL = tid >> 1, seg32 = (tid & 1) << 5;

    auto issue_chunk = [&](int c) {
        uint32_t stb = sbase + (uint32_t)(c & 3) * CSTAGE;
        uint32_t sa = stb + (uint32_t)rowL * CSROW + seg32;
        const __half* ga = A + (long)rowL * 1024 + (c << 5) + (seg32 >> 1);
        CP_ASYNC16(sa, ga);
        CP_ASYNC16(sa + 16, ga + 8);
        uint32_t sb = stb + CB_OFF + (uint32_t)rowL * CSROW + seg32;
        const __half* gb = B + (long)rowL * 1024 + (c << 5) + (seg32 >> 1);
        CP_ASYNC16(sb, gb);
        CP_ASYNC16(sb + 16, gb + 8);
        CP_COMMIT();
    };

    issue_chunk(0); issue_chunk(1); issue_chunk(2);

    for (int c = 0; c < 32; c++) {
        CP_WAIT2();
        __syncthreads();
        if (c + 3 < 32) issue_chunk(c + 3); else CP_COMMIT();

        uint32_t stb = sbase + (uint32_t)(c & 3) * CSTAGE;
#pragma unroll
        for (int kh = 0; kh < 2; kh++) {
            uint32_t ko = (uint32_t)(kh << 5);
            uint32_t af[4][4], bf[2][4];
#pragma unroll
            for (int fm = 0; fm < 4; fm++)
                LDSM_X4(af[fm][0], af[fm][1], af[fm][2], af[fm][3], stb + ofsA[fm] + ko);
#pragma unroll
            for (int j = 0; j < 2; j++)
                LDSM_X4(bf[j][0], bf[j][1], bf[j][2], bf[j][3], stb + ofsB[j] + ko);
#pragma unroll
            for (int fm = 0; fm < 4; fm++)
#pragma unroll
                for (int fn = 0; fn < 4; fn++)
                    mma_f16(acc[fm][fn], af[fm], &bf[fn >> 1][(fn & 1) << 1]);
        }
    }
    CP_WAITALL();

    // -------- epilogue: transpose via smem, parity-scatter chan-major stores --------
    __syncthreads();
    float* Dsh = sh;
    int g = lane >> 2, tq = lane & 3;
#pragma unroll
    for (int fm = 0; fm < 4; fm++) {
        int m = (wm << 6) + (fm << 4) + g;
#pragma unroll
        for (int fn = 0; fn < 4; fn++) {
            int n = (wn << 5) + (fn << 3) + (tq << 1);
            Dsh[n * DST + m]           = acc[fm][fn][0];
            Dsh[(n + 1) * DST + m]     = acc[fm][fn][1];
            Dsh[n * DST + m + 8]       = acc[fm][fn][2];
            Dsh[(n + 1) * DST + m + 8] = acc[fm][fn][3];
        }
    }
    __syncthreads();
    int az = par >> 2, ay = (par >> 1) & 1, ax = par & 1;
    for (int i = tid; i < 4096; i += 256) {
        int n = i >> 5, cc = (i & 31) << 2;
        int pos = (posT << 7) + n;
        int iz = pos >> 6, iy = (pos >> 3) & 7, ix = pos & 7;
        int s = (2 * iz + az) * 256 + (2 * iy + ay) * 16 + 2 * ix + ax;
        float4 v = *reinterpret_cast<float4*>(&Dsh[n * DST + cc]);
        int co = (coT << 7) + cc;
        long ob = ((long)b * 1024 + 512 + co) * 4096 + s;
        out[ob]            = v.x + __ldg(&bt[co]);
        out[ob + 4096]     = v.y + __ldg(&bt[co + 1]);
        out[ob + 2 * 4096] = v.z + __ldg(&bt[co + 2]);
        out[ob + 3 * 4096] = v.w + __ldg(&bt[co + 3]);
    }
}

// ---------------- launcher ----------------
extern "C" void kernel_launch(void* const* d_in, const int* in_sizes, int n_in,
                              void* d_out, int out_size)
{
    const float* pc  = (const float*)d_in[0];
    const float* W1  = (const float*)d_in[1];
    const float* b1  = (const float*)d_in[2];
    const float* W2  = (const float*)d_in[3];
    const float* b2  = (const float*)d_in[4];
    const float* Wc1 = (const float*)d_in[5];
    const float* bc1 = (const float*)d_in[6];
    const float* Wc2 = (const float*)d_in[7];
    const float* bc2 = (const float*)d_in[8];
    const float* Wt  = (const float*)d_in[9];
    const float* bt  = (const float*)d_in[10];
    float* out = (float*)d_out;

    void *p_xpad, *p_xh, *p_wk1, *p_wk2, *p_l1h;
    cudaGetSymbolAddress(&p_xpad, g_xpad);
    cudaGetSymbolAddress(&p_xh, g_xh);
    cudaGetSymbolAddress(&p_wk1, g_wk1);
    cudaGetSymbolAddress(&p_wk2, g_wk2);
    cudaGetSymbolAddress(&p_l1h, g_l1h);

    const int smem_gm = 128 * DST * 4;                // 67,584 B (mainloop needs 59,136)
    const int smem_ct = 4 * CSTAGE;                   // 81,920 B (>= epilogue 67,584)
    cudaFuncSetAttribute(gemm_conv_halo, cudaFuncAttributeMaxDynamicSharedMemorySize, smem_gm);
    cudaFuncSetAttribute(convt_mma_kernel, cudaFuncAttributeMaxDynamicSharedMemorySize, smem_ct);
    cudaFuncSetAttribute(point_f_mma_kernel, cudaFuncAttributeMaxDynamicSharedMemorySize, PF_SMEM);

    // 1. zero scatter targets (replay-safe)
    zero_scratch_kernel<<<2048, 256>>>();
    // 2. weight conversions/transposes
    wt_transpose_kernel<<<16384, 256>>>(Wt);
    wk_transpose_kernel<<<4096, 256>>>(Wc1, (__half*)p_wk1, C1, C0);
    wk_transpose_kernel<<<8192, 256>>>(Wc2, (__half*)p_wk2, C2, C1);
    w2_half_kernel<<<128, 256>>>(W2);
    // 3. point MLP + scatter (fp16 mma)
    point_h_kernel<<<TOTPTS / 8, 256>>>(pc, W1, b1);
    point_f_mma_kernel<<<dim3(TOTPTS / 64, 2), 256, PF_SMEM>>>(b2);
    pack_half_kernel<<<2048, 256>>>((const float*)p_xpad, (__half*)p_xh, (long)(BATCH * NPAD1 * C0) / 4);
    // 4. conv1 + fused pool -> d_out l1 + g_l1h
    gemm_conv_halo<<<dim3(256, 4, BATCH), 256, smem_gm>>>(
        (const __half*)p_wk1, (const __half*)p_xh, bc1, out,
        C0, C0 / 16, SP1, C1, 4, 8, 1);
    // 5. conv2 + fused pool -> g_l2h
    gemm_conv_halo<<<dim3(32, 8, BATCH), 256, smem_gm>>>(
        (const __half*)p_wk2, (const __half*)p_l1h, bc2, nullptr,
        C1, C1 / 16, SP2, C2, 2, 4, 2);
    // 6. convT (fp16 mma) -> d_out[:,512:1024,:]
    convt_mma_kernel<<<dim3(4, 4, 16), 256, smem_ct>>>(bt, out);
}

// round 14
// speedup vs baseline: 1.8486x; 1.0656x over previous
#include <cuda_runtime.h>
#include <cuda_fp16.h>
#include <cstdint>

// ---------------- problem constants ----------------
#define BATCH 2
#define NPTS 100000
#define TOTPTS (BATCH * NPTS)
#define C0 256
#define C1 512
#define C2 1024
#define SP1 34                 // padded 32+2
#define NPAD1 (SP1*SP1*SP1)    // 39304
#define SP2 18                 // padded 16+2
#define NPAD2 (SP2*SP2*SP2)    // 5832
#define DST 132                // epilogue smem row stride (floats)
// halo-conv staging geometry (tile 8x(4)y(4)z, halo 10x6x6=360 rows)
#define AROW 48
#define BROW 48
#define A_STAGE 6144           // 128*AROW
#define B_BUF_OFF 24576        // 4*A_STAGE
#define B_BUF 17280            // 360*BROW
// point_f mma staging
#define PFST 272
#define PF_B_OFF 34816
#define PF_BASE_OFF 52224
#define PF_SMEM 52736
// convT mma staging
#define CSROW 80
#define CSTAGE 20480
#define CB_OFF 10240

// ---------------- device scratch ----------------
__device__ float  g_xpad[BATCH * NPAD1 * C0];    // fp32 scatter grid (atomics)
__device__ __half g_xh[BATCH * NPAD1 * C0];      // fp16 conv1 input
__device__ __half g_hh[TOTPTS * 128];            // point hidden fp16
__device__ __half g_w2h[256 * 128];              // W2 fp16
__device__ int    g_flat[TOTPTS];                // padded voxel index
__device__ __half g_wk1[27 * C1 * C0];           // conv1 W [k][co][ci] fp16
__device__ __half g_wk2[27 * C2 * C1];           // conv2 W [k][co][ci] fp16
__device__ __half g_l1h[BATCH * NPAD2 * C1];     // pooled l1, pos-major fp16 (zero ring)
__device__ __half g_l2h[BATCH * 512 * C2];       // pooled l2, pos-major fp16
__device__ __half g_wtTh[8 * 512 * 1024];        // convT W (par, co, ci) fp16

// ---------------- helpers ----------------
__device__ __forceinline__ uint32_t smem_u32p(const void* p) {
    uint32_t a;
    asm("{ .reg .u64 t; cvta.to.shared.u64 t, %1; cvt.u32.u64 %0, t; }" : "=r"(a) : "l"(p));
    return a;
}
__device__ __forceinline__ void mma_f16(float* c, const uint32_t* a, const uint32_t* b) {
    asm volatile(
        "mma.sync.aligned.m16n8k16.row.col.f32.f16.f16.f32 "
        "{%0,%1,%2,%3}, {%4,%5,%6,%7}, {%8,%9}, {%0,%1,%2,%3};\n"
        : "+f"(c[0]), "+f"(c[1]), "+f"(c[2]), "+f"(c[3])
        : "r"(a[0]), "r"(a[1]), "r"(a[2]), "r"(a[3]), "r"(b[0]), "r"(b[1]));
}
#define LDSM_X4(r0, r1, r2, r3, addr) \
    asm volatile("ldmatrix.sync.aligned.m8n8.x4.shared.b16 {%0,%1,%2,%3}, [%4];" \
        : "=r"(r0), "=r"(r1), "=r"(r2), "=r"(r3) : "r"(addr))
#define CP_ASYNC16(sa, ga) \
    asm volatile("cp.async.cg.shared.global [%0], [%1], 16;" :: "r"(sa), "l"(ga) : "memory")
#define CP_COMMIT() asm volatile("cp.async.commit_group;" ::: "memory")
#define CP_WAIT2()  asm volatile("cp.async.wait_group 2;" ::: "memory")
#define CP_WAITALL() asm volatile("cp.async.wait_all;" ::: "memory")

// ---------------- zero scratch (replay-safe) ----------------
__global__ void zero_scratch_kernel() {
    float4* p1 = reinterpret_cast<float4*>(g_xpad);
    int n1 = (BATCH * NPAD1 * C0) / 4;
    for (int i = blockIdx.x * blockDim.x + threadIdx.x; i < n1; i += gridDim.x * blockDim.x)
        p1[i] = make_float4(0.f, 0.f, 0.f, 0.f);
    float4* p2 = reinterpret_cast<float4*>(g_l1h);
    int n2 = (BATCH * NPAD2 * C1) / 8;
    for (int i = blockIdx.x * blockDim.x + threadIdx.x; i < n2; i += gridDim.x * blockDim.x)
        p2[i] = make_float4(0.f, 0.f, 0.f, 0.f);
}

// ---------------- pack fp32 grid -> fp16 ----------------
__global__ void pack_half_kernel(const float* __restrict__ src, __half* __restrict__ dst, long n4) {
    for (long i = (long)blockIdx.x * blockDim.x + threadIdx.x; i < n4; i += (long)gridDim.x * blockDim.x) {
        float4 v = reinterpret_cast<const float4*>(src)[i];
        __half2* d = reinterpret_cast<__half2*>(dst) + 2 * i;
        d[0] = __floats2half2_rn(v.x, v.y);
        d[1] = __floats2half2_rn(v.z, v.w);
    }
}

// ---------------- W2 -> fp16 ----------------
__global__ void w2_half_kernel(const float* __restrict__ W2) {
    int i = blockIdx.x * blockDim.x + threadIdx.x;
    if (i < 256 * 128) g_w2h[i] = __float2half_rn(W2[i]);
}

// ---------------- conv weight transpose (smem-staged, coalesced both sides) ----------------
// block: 256 consecutive (co,ci) pairs; read 256*27 contiguous floats; write 27 runs of 256 halves.
__global__ __launch_bounds__(256) void wk_transpose_kernel(
    const float* __restrict__ w, __half* __restrict__ wk, int Cout, int Cin)
{
    __shared__ __half sm[256 * 28];
    int tid = threadIdx.x;
    long base = (long)blockIdx.x * 256;
    const float* src = w + base * 27;
    for (int j = tid; j < 256 * 27; j += 256) {
        int pair = j / 27, k = j - pair * 27;
        sm[pair * 28 + k] = __float2half_rn(src[j]);
    }
    __syncthreads();
    long CC = (long)Cout * Cin;
#pragma unroll
    for (int k = 0; k < 27; k++)
        wk[(long)k * CC + base + tid] = sm[tid * 28 + k];
}

// ---------------- convT weight transpose (smem 32x32 tile, coalesced) ----------------
__global__ __launch_bounds__(256) void wt_transpose_kernel(const float* __restrict__ Wt) {
    __shared__ __half tile[8][32][33];
    int tid = threadIdx.x;
    int coT = blockIdx.x, ciT = blockIdx.y;
#pragma unroll
    for (int p = 0; p < 4; p++) {
        int idx = p * 256 + tid;
        int co_l = idx & 31, ci_l = idx >> 5;
        int co = coT * 32 + co_l, ci = ciT * 32 + ci_l;
        float4 a = *reinterpret_cast<const float4*>(&Wt[(long)ci * 4096 + co * 8]);
        float4 b = *reinterpret_cast<const float4*>(&Wt[(long)ci * 4096 + co * 8 + 4]);
        tile[0][co_l][ci_l] = __float2half_rn(a.x);
        tile[1][co_l][ci_l] = __float2half_rn(a.y);
        tile[2][co_l][ci_l] = __float2half_rn(a.z);
        tile[3][co_l][ci_l] = __float2half_rn(a.w);
        tile[4][co_l][ci_l] = __float2half_rn(b.x);
        tile[5][co_l][ci_l] = __float2half_rn(b.y);
        tile[6][co_l][ci_l] = __float2half_rn(b.z);
        tile[7][co_l][ci_l] = __float2half_rn(b.w);
    }
    __syncthreads();
#pragma unroll
    for (int p = 0; p < 16; p++) {
        int idx = p * 256 + tid;
        int ci2 = idx & 15, co_l = (idx >> 4) & 31, par = idx >> 9;
        int co = coT * 32 + co_l, ci = ciT * 32 + ci2 * 2;
        __half2 v = __halves2half2(tile[par][co_l][ci2 * 2], tile[par][co_l][ci2 * 2 + 1]);
        *reinterpret_cast<__half2*>(&g_wtTh[(((long)par * 512 + co) << 10) + ci]) = v;
    }
}

// ---------------- point MLP stage 1 (fp16 h out) ----------------
__global__ __launch_bounds__(256) void point_h_kernel(
    const float* __restrict__ pc, const float* __restrict__ W1, const float* __restrict__ b1)
{
    __shared__ float W1s[384];
    __shared__ float b1s[128];
    int tid = threadIdx.x;
    for (int i = tid; i < 384; i += 256) W1s[i] = W1[i];
    if (tid < 128) b1s[tid] = b1[tid];
    __syncthreads();

    int P = blockIdx.x * 8 + (tid >> 5);
    int lane = tid & 31;
    if (P >= TOTPTS) return;

    float x = pc[P * 3 + 0], y = pc[P * 3 + 1], z = pc[P * 3 + 2];
    int ix = (int)floorf((x + 1.0f) * 16.0f);
    int iy = (int)floorf((y + 1.0f) * 16.0f);
    int iz = (int)floorf((z + 1.0f) * 16.0f);
    float xcx = x - (ix * 0.0625f + 0.03125f - 1.0f);
    float xcy = y - (iy * 0.0625f + 0.03125f - 1.0f);
    float xcz = z - (iz * 0.0625f + 0.03125f - 1.0f);

    if (lane == 0) g_flat[P] = (ix + 1) * (SP1 * SP1) + (iy + 1) * SP1 + (iz + 1);

    __half* hrow = g_hh + (long)P * 128;
#pragma unroll
    for (int j = 0; j < 4; j++) {
        int o = lane + 32 * j;
        float v = W1s[o * 3 + 0] * xcx + W1s[o * 3 + 1] * xcy + W1s[o * 3 + 2] * xcz + b1s[o];
        hrow[o] = __float2half_rn(fmaxf(v, 0.0f));
    }
}

// ---------------- point MLP stage 2: fp16 mma + scatter-max ----------------
__global__ __launch_bounds__(256) void point_f_mma_kernel(const float* __restrict__ b2) {
    extern __shared__ char pfs[];
    uint32_t sbase = smem_u32p(pfs);
    uint32_t Ab = sbase, Bb = sbase + PF_B_OFF;
    long* bases = reinterpret_cast<long*>(pfs + PF_BASE_OFF);

    int tid = threadIdx.x;
    int lane = tid & 31, wid = tid >> 5;
    int wm = wid >> 2, wn = wid & 3;
    int P0 = blockIdx.x * 64;
    int co0 = blockIdx.y << 7;

    {
        const __half* w2 = g_w2h + (long)co0 * 128;
        for (int idx = tid; idx < 2048; idx += 256) {
            int r = idx >> 4, s = idx & 15;
            CP_ASYNC16(Ab + (uint32_t)r * PFST + (s << 4), w2 + r * 128 + s * 8);
        }
        const __half* hsrc = g_hh + (long)P0 * 128;
        for (int idx = tid; idx < 1024; idx += 256) {
            int r = idx >> 4, s = idx & 15;
            CP_ASYNC16(Bb + (uint32_t)r * PFST + (s << 4), hsrc + r * 128 + s * 8);
        }
        CP_COMMIT();
        if (tid < 64) {
            int P = P0 + tid;
            bases[tid] = ((long)(P / NPTS) * NPAD1 + g_flat[P]) * C0;
        }
        CP_WAITALL();
        __syncthreads();
    }

    uint32_t ofsA[4];
#pragma unroll
    for (int fm = 0; fm < 4; fm++)
        ofsA[fm] = (uint32_t)(((wm << 6) + (fm << 4) + (lane & 15)) * PFST + ((lane >> 4) << 4));
    uint32_t ofsB = (uint32_t)(((wn << 4) + (lane & 7) + ((lane >> 4) << 3)) * PFST
                   + (((lane >> 3) & 1) << 4));

    float acc[4][2][4];
#pragma unroll
    for (int fm = 0; fm < 4; fm++)
#pragma unroll
        for (int fn = 0; fn < 2; fn++)
#pragma unroll
            for (int r = 0; r < 4; r++) acc[fm][fn][r] = 0.0f;

#pragma unroll
    for (int ks = 0; ks < 8; ks++) {
        uint32_t ko = (uint32_t)(ks << 5);
        uint32_t af[4][4], bf[4];
#pragma unroll
        for (int fm = 0; fm < 4; fm++)
            LDSM_X4(af[fm][0], af[fm][1], af[fm][2], af[fm][3], Ab + ofsA[fm] + ko);
        LDSM_X4(bf[0], bf[1], bf[2], bf[3], Bb + ofsB + ko);
#pragma unroll
        for (int fm = 0; fm < 4; fm++)
#pragma unroll
            for (int fn = 0; fn < 2; fn++)
                mma_f16(acc[fm][fn], af[fm], &bf[fn << 1]);
    }

    int g = lane >> 2, t = lane & 3;
    int* gx = reinterpret_cast<int*>(g_xpad);
#pragma unroll
    for (int fm = 0; fm < 4; fm++) {
        int m0 = (wm << 6) + (fm << 4) + g;
        float bv0 = __ldg(&b2[co0 + m0]);
        float bv1 = __ldg(&b2[co0 + m0 + 8]);
#pragma unroll
        for (int fn = 0; fn < 2; fn++) {
            int n0 = (wn << 4) + (fn << 3) + (t << 1);
            long ba0 = bases[n0] + co0, ba1 = bases[n0 + 1] + co0;
            float f;
            f = acc[fm][fn][0] + bv0; if (f > 0.f) atomicMax(&gx[ba0 + m0], __float_as_int(f));
            f = acc[fm][fn][1] + bv0; if (f > 0.f) atomicMax(&gx[ba1 + m0], __float_as_int(f));
            f = acc[fm][fn][2] + bv1; if (f > 0.f) atomicMax(&gx[ba0 + m0 + 8], __float_as_int(f));
            f = acc[fm][fn][3] + bv1; if (f > 0.f) atomicMax(&gx[ba1 + m0 + 8], __float_as_int(f));
        }
    }
}

// ---------------- fp16 mma halo-tiled conv3x3x3 + FUSED bias/relu/maxpool ----------------
// 128 threads: 4 warps in 2(M)x2(N), warp tile 64co x 64pos (lower smem-crossbar duplication).
// mode 1: write d_out l1 (fp32 chan-major) + g_l1h; mode 2: write g_l2h.
__global__ __launch_bounds__(128, 2) void gemm_conv_halo(
    const __half* __restrict__ wk, const __half* __restrict__ xp,
    const float* __restrict__ bias, float* __restrict__ dout,
    int Cin, int nChunks, int Sp, int Cout, int ntx, int nty, int mode)
{
    extern __shared__ float sh[];
    uint32_t sbase = smem_u32p(sh);
    int tid = threadIdx.x;
    int lane = tid & 31, wid = tid >> 5;
    int wm = wid >> 1, wn = wid & 1;

    int t = blockIdx.x;
    int tix = t % ntx; int tr = t / ntx; int tiy = tr % nty; int tiz = tr / nty;
    int px0 = 1 + tix * 8, py0 = 1 + tiy * 4, pz0 = 1 + tiz * 4;
    int SPsq = Sp * Sp;
    int bz = blockIdx.z;
    long bq = (long)bz * (Sp * SPsq);
    int M0 = blockIdx.y << 7;
    long row0 = (long)(pz0 - 1) * SPsq + (long)(py0 - 1) * Sp + (px0 - 1);
    int total = nChunks * 27;

    uint32_t ofsA[4];
#pragma unroll
    for (int fm = 0; fm < 4; fm++)
        ofsA[fm] = (uint32_t)(((wm << 6) + (fm << 4) + (lane & 15)) * AROW + ((lane >> 4) << 4));
    uint32_t hofs[4];
    uint32_t kbyte = (uint32_t)(((lane >> 3) & 1) << 4);
#pragma unroll
    for (int j = 0; j < 4; j++) {
        int n = (wn << 6) + (j << 4) + (lane & 7) + ((lane >> 4) << 3);
        int nx = n & 7, ny = (n >> 3) & 3, nz = n >> 5;
        hofs[j] = (uint32_t)((nz * 60 + ny * 10 + nx) * BROW) + kbyte;
    }

    float acc[4][8][4];
#pragma unroll
    for (int fm = 0; fm < 4; fm++)
#pragma unroll
        for (int fn = 0; fn < 8; fn++)
#pragma unroll
            for (int r = 0; r < 4; r++) acc[fm][fn][r] = 0.0f;

    auto issue_stage = [&](int sIdx, int c, int tap, bool withB, int cb) {
        uint32_t stA = sbase + (uint32_t)sIdx * A_STAGE;
        uint32_t sa = stA + (uint32_t)tid * AROW;
        const __half* ga = wk + ((long)tap * Cout + M0 + tid) * Cin + (c << 4);
        CP_ASYNC16(sa, ga);
        CP_ASYNC16(sa + 16, ga + 8);
        if (withB) {
            uint32_t stB = sbase + B_BUF_OFF + (uint32_t)(cb & 1) * B_BUF;
            for (int s = tid; s < 720; s += 128) {
                int hr = s >> 1, hseg = s & 1;
                int hz = hr / 60; int h2 = hr - hz * 60;
                int hy = h2 / 10; int hx = h2 - hy * 10;
                long gpos = row0 + (long)hz * SPsq + hy * Sp + hx;
                const __half* gb = xp + (bq + gpos) * Cin + (cb << 4) + (hseg << 3);
                CP_ASYNC16(stB + (uint32_t)hr * BROW + (hseg << 4), gb);
            }
        }
        CP_COMMIT();
    };

    issue_stage(0, 0, 0, true, 0);
    issue_stage(1, 0, 1, false, 0);
    issue_stage(2, 0, 2, false, 0);

    int cI = 0, tapI = 3;
    int cU = 0, dxU = 0, dyU = 0, dzU = 0;

    for (int u = 0; u < total; u++) {
        CP_WAIT2();
        __syncthreads();
        if (u + 3 < total) {
            bool wB = (tapI == 24) && (cI + 1 < nChunks);
            issue_stage((u + 3) & 3, cI, tapI, wB, cI + 1);
            if (++tapI == 27) { tapI = 0; cI++; }
        } else CP_COMMIT();

        uint32_t stA = sbase + (uint32_t)(u & 3) * A_STAGE;
        uint32_t stB = sbase + B_BUF_OFF + (uint32_t)(cU & 1) * B_BUF
                     + (uint32_t)((dzU * 60 + dyU * 10 + dxU) * BROW);
        uint32_t af[4][4], bf[4][4];
#pragma unroll
        for (int fm = 0; fm < 4; fm++)
            LDSM_X4(af[fm][0], af[fm][1], af[fm][2], af[fm][3], stA + ofsA[fm]);
#pragma unroll
        for (int j = 0; j < 4; j++)
            LDSM_X4(bf[j][0], bf[j][1], bf[j][2], bf[j][3], stB + hofs[j]);
#pragma unroll
        for (int fm = 0; fm < 4; fm++)
#pragma unroll
            for (int fn = 0; fn < 8; fn++)
                mma_f16(acc[fm][fn], af[fm], &bf[fn >> 1][(fn & 1) << 1]);

        if (++dxU == 3) { dxU = 0; if (++dyU == 3) { dyU = 0; if (++dzU == 3) { dzU = 0; cU++; } } }
    }
    CP_WAITALL();

    // -------- epilogue: transpose via smem, FUSED 2x2x2 maxpool + bias + relu --------
    __syncthreads();
    float* Dsh = sh;
    int g = lane >> 2, tq = lane & 3;
#pragma unroll
    for (int fm = 0; fm < 4; fm++) {
        int m = (wm << 6) + (fm << 4) + g;
#pragma unroll
        for (int fn = 0; fn < 8; fn++) {
            int n = (wn << 6) + (fn << 3) + (tq << 1);
            Dsh[n * DST + m]           = acc[fm][fn][0];
            Dsh[(n + 1) * DST + m]     = acc[fm][fn][1];
            Dsh[n * DST + m + 8]       = acc[fm][fn][2];
            Dsh[(n + 1) * DST + m + 8] = acc[fm][fn][3];
        }
    }
    __syncthreads();
    for (int i = tid; i < 512; i += 128) {
        int cc = (i & 31) << 2;
        int pcell = i >> 5;
        int jx = pcell & 3, jy = (pcell >> 2) & 1, jz = pcell >> 3;
        float4 m = make_float4(-1e30f, -1e30f, -1e30f, -1e30f);
#pragma unroll
        for (int d = 0; d < 8; d++) {
            int n = ((jz * 2 + (d >> 2)) << 5) + ((jy * 2 + ((d >> 1) & 1)) << 3) + (jx * 2 + (d & 1));
            float4 v = *reinterpret_cast<float4*>(&Dsh[n * DST + cc]);
            m.x = fmaxf(m.x, v.x); m.y = fmaxf(m.y, v.y); m.z = fmaxf(m.z, v.z); m.w = fmaxf(m.w, v.w);
        }
        m.x = fmaxf(m.x + __ldg(&bias[M0 + cc + 0]), 0.f);
        m.y = fmaxf(m.y + __ldg(&bias[M0 + cc + 1]), 0.f);
        m.z = fmaxf(m.z + __ldg(&bias[M0 + cc + 2]), 0.f);
        m.w = fmaxf(m.w + __ldg(&bias[M0 + cc + 3]), 0.f);
        int PX = (tix << 2) + jx, PY = (tiy << 1) + jy, PZ = (tiz << 1) + jz;
        if (mode == 1) {
            int s = PZ * 256 + PY * 16 + PX;
            long ob = ((long)bz * 1024 + M0 + cc) * 4096 + s;
            dout[ob] = m.x; dout[ob + 4096] = m.y; dout[ob + 2 * 4096] = m.z; dout[ob + 3 * 4096] = m.w;
            int pad2 = (PZ + 1) * (SP2 * SP2) + (PY + 1) * SP2 + (PX + 1);
            __half2* lh = reinterpret_cast<__half2*>(&g_l1h[((long)bz * NPAD2 + pad2) * C1 + M0 + cc]);
            lh[0] = __floats2half2_rn(m.x, m.y);
            lh[1] = __floats2half2_rn(m.z, m.w);
        } else {
            int pp = PZ * 64 + PY * 8 + PX;
            __half2* lh = reinterpret_cast<__half2*>(&g_l2h[((long)bz * 512 + pp) * C2 + M0 + cc]);
            lh[0] = __floats2half2_rn(m.x, m.y);
            lh[1] = __floats2half2_rn(m.z, m.w);
        }
    }
}

// ---------------- convT: fp16 mma parity GEMMs ----------------
__global__ __launch_bounds__(256, 2) void convt_mma_kernel(
    const float* __restrict__ bt, float* __restrict__ out)
{
    extern __shared__ float sh[];
    uint32_t sbase = smem_u32p(sh);
    int tid = threadIdx.x;
    int lane = tid & 31, wid = tid >> 5;
    int wm = wid >> 2, wn = wid & 3;
    int posT = blockIdx.x, coT = blockIdx.y;
    int bp = blockIdx.z;
    int b = bp >> 3, par = bp & 7;

    const __half* A = g_wtTh + (long)par * (512 * 1024) + (long)(coT << 7) * 1024;
    const __half* B = g_l2h + (long)b * (512 * 1024) + (long)(posT << 7) * 1024;

    uint32_t ofsA[4], ofsB[2];
#pragma unroll
    for (int fm = 0; fm < 4; fm++)
        ofsA[fm] = (uint32_t)(((wm << 6) + (fm << 4) + (lane & 15)) * CSROW + ((lane >> 4) << 4));
#pragma unroll
    for (int j = 0; j < 2; j++) {
        int row = (wn << 5) + (j << 4) + (lane & 7) + ((lane >> 4) << 3);
        ofsB[j] = (uint32_t)(CB_OFF + row * CSROW + (((lane >> 3) & 1) << 4));
    }

    float acc[4][4][4];
#pragma unroll
    for (int fm = 0; fm < 4; fm++)
#pragma unroll
        for (int fn = 0; fn < 4; fn++)
#pragma unroll
            for (int r = 0; r < 4; r++) acc[fm][fn][r] = 0.0f;

    int rowL = tid >> 1, seg32 = (tid & 1) << 5;

    auto issue_chunk = [&](int c) {
        uint32_t stb = sbase + (uint32_t)(c & 3) * CSTAGE;
        uint32_t sa = stb + (uint32_t)rowL * CSROW + seg32;
        const __half* ga = A + (long)rowL * 1024 + (c << 5) + (seg32 >> 1);
        CP_ASYNC16(sa, ga);
        CP_ASYNC16(sa + 16, ga + 8);
        uint32_t sb = stb + CB_OFF + (uint32_t)rowL * CSROW + seg32;
        const __half* gb = B + (long)rowL * 1024 + (c << 5) + (seg32 >> 1);
        CP_ASYNC16(sb, gb);
        CP_ASYNC16(sb + 16, gb + 8);
        CP_COMMIT();
    };

    issue_chunk(0); issue_chunk(1); issue_chunk(2);

    for (int c = 0; c < 32; c++) {
        CP_WAIT2();
        __syncthreads();
        if (c + 3 < 32) issue_chunk(c + 3); else CP_COMMIT();

        uint32_t stb = sbase + (uint32_t)(c & 3) * CSTAGE;
#pragma unroll
        for (int kh = 0; kh < 2; kh++) {
            uint32_t ko = (uint32_t)(kh << 5);
            uint32_t af[4][4], bf[2][4];
#pragma unroll
            for (int fm = 0; fm < 4; fm++)
                LDSM_X4(af[fm][0], af[fm][1], af[fm][2], af[fm][3], stb + ofsA[fm] + ko);
#pragma unroll
            for (int j = 0; j < 2; j++)
                LDSM_X4(bf[j][0], bf[j][1], bf[j][2], bf[j][3], stb + ofsB[j] + ko);
#pragma unroll
            for (int fm = 0; fm < 4; fm++)
#pragma unroll
                for (int fn = 0; fn < 4; fn++)
                    mma_f16(acc[fm][fn], af[fm], &bf[fn >> 1][(fn & 1) << 1]);
        }
    }
    CP_WAITALL();

    __syncthreads();
    float* Dsh = sh;
    int g = lane >> 2, tq = lane & 3;
#pragma unroll
    for (int fm = 0; fm < 4; fm++) {
        int m = (wm << 6) + (fm << 4) + g;
#pragma unroll
        for (int fn = 0; fn < 4; fn++) {
            int n = (wn << 5) + (fn << 3) + (tq << 1);
            Dsh[n * DST + m]           = acc[fm][fn][0];
            Dsh[(n + 1) * DST + m]     = acc[fm][fn][1];
            Dsh[n * DST + m + 8]       = acc[fm][fn][2];
            Dsh[(n + 1) * DST + m + 8] = acc[fm][fn][3];
        }
    }
    __syncthreads();
    int az = par >> 2, ay = (par >> 1) & 1, ax = par & 1;
    for (int i = tid; i < 4096; i += 256) {
        int n = i >> 5, cc = (i & 31) << 2;
        int pos = (posT << 7) + n;
        int iz = pos >> 6, iy = (pos >> 3) & 7, ix = pos & 7;
        int s = (2 * iz + az) * 256 + (2 * iy + ay) * 16 + 2 * ix + ax;
        float4 v = *reinterpret_cast<float4*>(&Dsh[n * DST + cc]);
        int co = (coT << 7) + cc;
        long ob = ((long)b * 1024 + 512 + co) * 4096 + s;
        out[ob]            = v.x + __ldg(&bt[co]);
        out[ob + 4096]     = v.y + __ldg(&bt[co + 1]);
        out[ob + 2 * 4096] = v.z + __ldg(&bt[co + 2]);
        out[ob + 3 * 4096] = v.w + __ldg(&bt[co + 3]);
    }
}

// ---------------- launcher ----------------
extern "C" void kernel_launch(void* const* d_in, const int* in_sizes, int n_in,
                              void* d_out, int out_size)
{
    const float* pc  = (const float*)d_in[0];
    const float* W1  = (const float*)d_in[1];
    const float* b1  = (const float*)d_in[2];
    const float* W2  = (const float*)d_in[3];
    const float* b2  = (const float*)d_in[4];
    const float* Wc1 = (const float*)d_in[5];
    const float* bc1 = (const float*)d_in[6];
    const float* Wc2 = (const float*)d_in[7];
    const float* bc2 = (const float*)d_in[8];
    const float* Wt  = (const float*)d_in[9];
    const float* bt  = (const float*)d_in[10];
    float* out = (float*)d_out;

    void *p_xpad, *p_xh, *p_wk1, *p_wk2, *p_l1h;
    cudaGetSymbolAddress(&p_xpad, g_xpad);
    cudaGetSymbolAddress(&p_xh, g_xh);
    cudaGetSymbolAddress(&p_wk1, g_wk1);
    cudaGetSymbolAddress(&p_wk2, g_wk2);
    cudaGetSymbolAddress(&p_l1h, g_l1h);

    const int smem_gm = 128 * DST * 4;                // 67,584 B (mainloop needs 59,136)
    const int smem_ct = 4 * CSTAGE;                   // 81,920 B
    cudaFuncSetAttribute(gemm_conv_halo, cudaFuncAttributeMaxDynamicSharedMemorySize, smem_gm);
    cudaFuncSetAttribute(convt_mma_kernel, cudaFuncAttributeMaxDynamicSharedMemorySize, smem_ct);
    cudaFuncSetAttribute(point_f_mma_kernel, cudaFuncAttributeMaxDynamicSharedMemorySize, PF_SMEM);

    // 1. zero scatter targets (replay-safe)
    zero_scratch_kernel<<<2048, 256>>>();
    // 2. weight conversions/transposes (coalesced)
    wt_transpose_kernel<<<dim3(16, 32), 256>>>(Wt);
    wk_transpose_kernel<<<(C1 * C0) / 256, 256>>>(Wc1, (__half*)p_wk1, C1, C0);
    wk_transpose_kernel<<<(C2 * C1) / 256, 256>>>(Wc2, (__half*)p_wk2, C2, C1);
    w2_half_kernel<<<128, 256>>>(W2);
    // 3. point MLP + scatter (fp16 mma)
    point_h_kernel<<<TOTPTS / 8, 256>>>(pc, W1, b1);
    point_f_mma_kernel<<<dim3(TOTPTS / 64, 2), 256, PF_SMEM>>>(b2);
    pack_half_kernel<<<2048, 256>>>((const float*)p_xpad, (__half*)p_xh, (long)(BATCH * NPAD1 * C0) / 4);
    // 4. conv1 + fused pool -> d_out l1 + g_l1h
    gemm_conv_halo<<<dim3(256, 4, BATCH), 128, smem_gm>>>(
        (const __half*)p_wk1, (const __half*)p_xh, bc1, out,
        C0, C0 / 16, SP1, C1, 4, 8, 1);
    // 5. conv2 + fused pool -> g_l2h
    gemm_conv_halo<<<dim3(32, 8, BATCH), 128, smem_gm>>>(
        (const __half*)p_wk2, (const __half*)p_l1h, bc2, nullptr,
        C1, C1 / 16, SP2, C2, 2, 4, 2);
    // 6. convT (fp16 mma) -> d_out[:,512:1024,:]
    convt_mma_kernel<<<dim3(4, 4, 16), 256, smem_ct>>>(bt, out);
}